// round 1
// baseline (speedup 1.0000x reference)
#include <cuda_runtime.h>
#include <math.h>

#define B_   2
#define N_   2048
#define C_   1024
#define H_   16
#define D_   64
#define M_   (B_ * N_)      // 4096
#define QKVN 3072

// ---------------- scratch (static device globals; no allocs allowed) --------
__device__ float g_qkv[(size_t)M_ * QKVN];      // 48 MB
__device__ float g_q[(size_t)B_ * H_ * N_ * D_]; // 16 MB  [b][h][n][d]
__device__ float g_k[(size_t)B_ * H_ * N_ * D_];
__device__ float g_v[(size_t)B_ * H_ * N_ * D_];
__device__ float g_ao[(size_t)M_ * C_];          // 16 MB  [b][n][h*64+d]

// ---------------- generic C = A @ B^T (+bias) sgemm, 128x128x8 --------------
// A: [M,K] row-major, Bw: [Nn,K] row-major, C: [M,Nn]. M,Nn % 128 == 0, K % 8 == 0.
__global__ void __launch_bounds__(256) sgemm_abt(
    const float* __restrict__ A, const float* __restrict__ Bw,
    const float* __restrict__ bias, float* __restrict__ C,
    int M, int Nn, int K)
{
    __shared__ float As[8][128];
    __shared__ float Bs[8][128];
    const int tid = threadIdx.x;
    const int tx = tid & 15, ty = tid >> 4;
    const int bm = blockIdx.y << 7, bn = blockIdx.x << 7;
    const int lr = tid >> 1;            // 0..127
    const int lc = (tid & 1) << 2;      // 0 or 4
    const float* Ap = A  + (size_t)(bm + lr) * K + lc;
    const float* Bp = Bw + (size_t)(bn + lr) * K + lc;

    float acc[8][8];
#pragma unroll
    for (int i = 0; i < 8; i++)
#pragma unroll
        for (int j = 0; j < 8; j++) acc[i][j] = 0.0f;

    for (int k0 = 0; k0 < K; k0 += 8) {
        float4 av = *(const float4*)(Ap + k0);
        float4 bv = *(const float4*)(Bp + k0);
        As[lc + 0][lr] = av.x; As[lc + 1][lr] = av.y;
        As[lc + 2][lr] = av.z; As[lc + 3][lr] = av.w;
        Bs[lc + 0][lr] = bv.x; Bs[lc + 1][lr] = bv.y;
        Bs[lc + 2][lr] = bv.z; Bs[lc + 3][lr] = bv.w;
        __syncthreads();
#pragma unroll
        for (int kk = 0; kk < 8; kk++) {
            float ar[8], br[8];
            *(float4*)(ar)     = *(const float4*)&As[kk][ty * 8];
            *(float4*)(ar + 4) = *(const float4*)&As[kk][ty * 8 + 4];
            *(float4*)(br)     = *(const float4*)&Bs[kk][tx * 8];
            *(float4*)(br + 4) = *(const float4*)&Bs[kk][tx * 8 + 4];
#pragma unroll
            for (int i = 0; i < 8; i++)
#pragma unroll
                for (int j = 0; j < 8; j++)
                    acc[i][j] = fmaf(ar[i], br[j], acc[i][j]);
        }
        __syncthreads();
    }

#pragma unroll
    for (int i = 0; i < 8; i++) {
        const size_t row = (size_t)(bm + ty * 8 + i);
        float out[8];
#pragma unroll
        for (int j = 0; j < 8; j++) {
            float bv = bias ? bias[bn + tx * 8 + j] : 0.0f;
            out[j] = acc[i][j] + bv;
        }
        float* cp = C + row * Nn + bn + tx * 8;
        *(float4*)(cp)     = *(const float4*)(out);
        *(float4*)(cp + 4) = *(const float4*)(out + 4);
    }
}

// ---------------- RoPE + split qkv -> q/k/v in [b][h][n][d] -----------------
// one block per (b,n); 512 threads = 16 heads x 32 lanes; lane i handles d=i and d=i+32
__global__ void __launch_bounds__(512) rope_split()
{
    const int m = blockIdx.x;          // 0..4095
    const int b = m >> 11, n = m & (N_ - 1);
    const int h = threadIdx.x >> 5;
    const int i = threadIdx.x & 31;

    const float* row = g_qkv + (size_t)m * QKVN;
    const int c = h * D_;
    float q0 = row[c + i],            q1 = row[c + i + 32];
    float k0 = row[C_ + c + i],       k1 = row[C_ + c + i + 32];
    float v0 = row[2 * C_ + c + i],   v1 = row[2 * C_ + c + i + 32];

    // inv_freq = 2048^(-i/32) = 2^(-11*i/32)   (exact: ROPE_BASE = 2^11)
    float inv = exp2f(-11.0f * (float)i * (1.0f / 32.0f));
    float th = (float)n * inv;
    float cs = cosf(th), sn = sinf(th);

    size_t base = (((size_t)b * H_ + h) * N_ + n) * D_;
    g_q[base + i]      = q0 * cs - q1 * sn;
    g_q[base + i + 32] = q1 * cs + q0 * sn;
    g_k[base + i]      = k0 * cs - k1 * sn;
    g_k[base + i + 32] = k1 * cs + k0 * sn;
    g_v[base + i]      = v0;
    g_v[base + i + 32] = v1;
}

// ---------------- flash attention, fp32, 64x64 tiles ------------------------
// grid: (N/64, H, B), 256 threads. Each thread: 4 q-rows x 4 cols (S) and
// 4 q-rows x 4 d-cols (O). Online softmax with key_padding bias.
#define BQ  64
#define BKV 64
#define LDP 65                      // padded row length in floats

extern __shared__ float sm_attn[];

__global__ void __launch_bounds__(256) flash_attn(const int* __restrict__ kpm)
{
    float* Qs = sm_attn;                 // [64][65]
    float* Ks = sm_attn + 64 * LDP;      // [64][65]
    float* Vs = sm_attn + 2 * 64 * LDP;  // [64][65]
    float* Ps = sm_attn + 3 * 64 * LDP;  // [64][65]  (P transposed: [c][r])
    float* mb = sm_attn + 4 * 64 * LDP;  // [64]

    const int b = blockIdx.z, h = blockIdx.y;
    const int q0 = blockIdx.x * BQ;
    const int tid = threadIdx.x;
    const int tx = tid & 15, ty = tid >> 4;

    const size_t head_off = ((size_t)b * H_ + h) * N_ * D_;
    const float* Qg = g_q + head_off + (size_t)q0 * D_;
    const float* Kg = g_k + head_off;
    const float* Vg = g_v + head_off;

    for (int idx = tid; idx < BQ * D_; idx += 256) {
        int r = idx >> 6, d = idx & 63;
        Qs[r * LDP + d] = Qg[idx];
    }

    float m_i[4], l_i[4], o[4][4];
#pragma unroll
    for (int ri = 0; ri < 4; ri++) {
        m_i[ri] = -INFINITY; l_i[ri] = 0.0f;
#pragma unroll
        for (int dj = 0; dj < 4; dj++) o[ri][dj] = 0.0f;
    }
    const float scale = 0.125f;   // 64^-0.5

    for (int kv0 = 0; kv0 < N_; kv0 += BKV) {
        __syncthreads();
        for (int idx = tid; idx < BKV * D_; idx += 256) {
            int r = idx >> 6, d = idx & 63;
            Ks[r * LDP + d] = Kg[kv0 * D_ + idx];
            Vs[r * LDP + d] = Vg[kv0 * D_ + idx];
        }
        if (tid < BKV)
            mb[tid] = (kpm[b * N_ + kv0 + tid] == 0) ? -1e9f : 0.0f;
        __syncthreads();

        // S = Q K^T
        float s[4][4];
#pragma unroll
        for (int ri = 0; ri < 4; ri++)
#pragma unroll
            for (int cj = 0; cj < 4; cj++) s[ri][cj] = 0.0f;

#pragma unroll 16
        for (int kk = 0; kk < D_; kk++) {
            float a[4], bb[4];
#pragma unroll
            for (int ri = 0; ri < 4; ri++) a[ri] = Qs[(ty * 4 + ri) * LDP + kk];
#pragma unroll
            for (int cj = 0; cj < 4; cj++) bb[cj] = Ks[(tx * 4 + cj) * LDP + kk];
#pragma unroll
            for (int ri = 0; ri < 4; ri++)
#pragma unroll
                for (int cj = 0; cj < 4; cj++)
                    s[ri][cj] = fmaf(a[ri], bb[cj], s[ri][cj]);
        }

        float mbias[4];
#pragma unroll
        for (int cj = 0; cj < 4; cj++) mbias[cj] = mb[tx * 4 + cj];
#pragma unroll
        for (int ri = 0; ri < 4; ri++)
#pragma unroll
            for (int cj = 0; cj < 4; cj++)
                s[ri][cj] = fmaf(s[ri][cj], scale, mbias[cj]);

        // online softmax update
        float mnew[4], alpha[4], rs[4];
#pragma unroll
        for (int ri = 0; ri < 4; ri++) {
            float v = s[ri][0];
#pragma unroll
            for (int cj = 1; cj < 4; cj++) v = fmaxf(v, s[ri][cj]);
#pragma unroll
            for (int off = 8; off >= 1; off >>= 1)
                v = fmaxf(v, __shfl_xor_sync(0xffffffffu, v, off));
            mnew[ri] = fmaxf(m_i[ri], v);
            alpha[ri] = __expf(m_i[ri] - mnew[ri]);
            m_i[ri] = mnew[ri];
        }
#pragma unroll
        for (int ri = 0; ri < 4; ri++) {
            float sum = 0.0f;
#pragma unroll
            for (int cj = 0; cj < 4; cj++) {
                s[ri][cj] = __expf(s[ri][cj] - mnew[ri]);
                sum += s[ri][cj];
            }
#pragma unroll
            for (int off = 8; off >= 1; off >>= 1)
                sum += __shfl_xor_sync(0xffffffffu, sum, off);
            rs[ri] = sum;
            l_i[ri] = l_i[ri] * alpha[ri] + rs[ri];
#pragma unroll
            for (int dj = 0; dj < 4; dj++) o[ri][dj] *= alpha[ri];
        }

        // stage P^T then O += P @ V
#pragma unroll
        for (int ri = 0; ri < 4; ri++)
#pragma unroll
            for (int cj = 0; cj < 4; cj++)
                Ps[(tx * 4 + cj) * LDP + ty * 4 + ri] = s[ri][cj];
        __syncthreads();

#pragma unroll 8
        for (int c = 0; c < BKV; c++) {
            float p[4], vv[4];
#pragma unroll
            for (int ri = 0; ri < 4; ri++) p[ri] = Ps[c * LDP + ty * 4 + ri];
#pragma unroll
            for (int dj = 0; dj < 4; dj++) vv[dj] = Vs[c * LDP + tx * 4 + dj];
#pragma unroll
            for (int ri = 0; ri < 4; ri++)
#pragma unroll
                for (int dj = 0; dj < 4; dj++)
                    o[ri][dj] = fmaf(p[ri], vv[dj], o[ri][dj]);
        }
    }

    // write O / l  to g_ao[b][n][h*64 + d]
#pragma unroll
    for (int ri = 0; ri < 4; ri++) {
        const float linv = 1.0f / l_i[ri];
        const int n = q0 + ty * 4 + ri;
        float* op = g_ao + ((size_t)(b * N_ + n)) * C_ + h * D_ + tx * 4;
#pragma unroll
        for (int dj = 0; dj < 4; dj++) op[dj] = o[ri][dj] * linv;
    }
}

// ---------------------------------------------------------------------------
extern "C" void kernel_launch(void* const* d_in, const int* in_sizes, int n_in,
                              void* d_out, int out_size)
{
    const float* x      = (const float*)d_in[0];
    const float* w_qkv  = (const float*)d_in[1];
    const float* w_proj = (const float*)d_in[2];
    const float* b_proj = (const float*)d_in[3];
    const int*   kpm    = (const int*)d_in[4];
    float* out = (float*)d_out;

    float *qkv, *ao;
    cudaGetSymbolAddress((void**)&qkv, g_qkv);
    cudaGetSymbolAddress((void**)&ao, g_ao);

    // 1) qkv = x @ w_qkv^T
    sgemm_abt<<<dim3(QKVN / 128, M_ / 128), 256>>>(x, w_qkv, nullptr, qkv,
                                                   M_, QKVN, C_);
    // 2) split + RoPE -> g_q/g_k/g_v
    rope_split<<<M_, 512>>>();

    // 3) flash attention -> g_ao
    const int smem = (4 * 64 * LDP + 64) * (int)sizeof(float);  // 66816 B
    cudaFuncSetAttribute(flash_attn, cudaFuncAttributeMaxDynamicSharedMemorySize, smem);
    flash_attn<<<dim3(N_ / BQ, H_, B_), 256, smem>>>(kpm);

    // 4) out = ao @ w_proj^T + b_proj
    sgemm_abt<<<dim3(C_ / 128, M_ / 128), 256>>>(ao, w_proj, b_proj, out,
                                                 M_, C_, C_);
}

// round 2
// speedup vs baseline: 1.0397x; 1.0397x over previous
#include <cuda_runtime.h>
#include <math.h>

#define B_   2
#define N_   2048
#define C_   1024
#define H_   16
#define D_   64
#define M_   (B_ * N_)      // 4096
#define QKVN 3072

typedef unsigned long long ull;

// ---------------- f32x2 packed-math helpers (Blackwell FFMA2) ---------------
__device__ __forceinline__ ull dup2(float x) {
    ull d; asm("mov.b64 %0, {%1, %1};" : "=l"(d) : "f"(x)); return d;
}
__device__ __forceinline__ ull pack2f(float lo, float hi) {
    ull d; asm("mov.b64 %0, {%1, %2};" : "=l"(d) : "f"(lo), "f"(hi)); return d;
}
__device__ __forceinline__ void unpack2f(ull v, float& lo, float& hi) {
    asm("mov.b64 {%0, %1}, %2;" : "=f"(lo), "=f"(hi) : "l"(v));
}
__device__ __forceinline__ ull ffma2(ull a, ull b, ull c) {
    ull d; asm("fma.rn.f32x2 %0, %1, %2, %3;" : "=l"(d) : "l"(a), "l"(b), "l"(c)); return d;
}
__device__ __forceinline__ ull fmul2(ull a, ull b) {
    ull d; asm("mul.rn.f32x2 %0, %1, %2;" : "=l"(d) : "l"(a), "l"(b)); return d;
}

// ---------------- scratch (static device globals; no allocs allowed) --------
__device__ float g_qkv[(size_t)M_ * QKVN];       // 48 MB
__device__ float g_q[(size_t)B_ * H_ * N_ * D_]; // 16 MB  [b][h][n][d]
__device__ float g_k[(size_t)B_ * H_ * N_ * D_];
__device__ float g_v[(size_t)B_ * H_ * N_ * D_];
__device__ float g_ao[(size_t)M_ * C_];          // 16 MB  [b][n][h*64+d]

// ---------------- generic C = A @ B^T (+bias) sgemm, 128x128x8, FFMA2 -------
// A: [M,K] row-major, Bw: [Nn,K] row-major, C: [M,Nn]. M,Nn % 128 == 0, K % 8 == 0.
__global__ void __launch_bounds__(256) sgemm_abt(
    const float* __restrict__ A, const float* __restrict__ Bw,
    const float* __restrict__ bias, float* __restrict__ C,
    int M, int Nn, int K)
{
    __shared__ float As[8][128];
    __shared__ float Bs[8][128];
    const int tid = threadIdx.x;
    const int tx = tid & 15, ty = tid >> 4;
    const int bm = blockIdx.y << 7, bn = blockIdx.x << 7;
    const int lr = tid >> 1;            // 0..127
    const int lc = (tid & 1) << 2;      // 0 or 4
    const float* Ap = A  + (size_t)(bm + lr) * K + lc;
    const float* Bp = Bw + (size_t)(bn + lr) * K + lc;

    ull acc2[8][4];   // 8 rows x 4 col-pairs (j = 2*jp, 2*jp+1)
#pragma unroll
    for (int i = 0; i < 8; i++)
#pragma unroll
        for (int jp = 0; jp < 4; jp++) acc2[i][jp] = 0ull;

    for (int k0 = 0; k0 < K; k0 += 8) {
        float4 av = *(const float4*)(Ap + k0);
        float4 bv = *(const float4*)(Bp + k0);
        As[lc + 0][lr] = av.x; As[lc + 1][lr] = av.y;
        As[lc + 2][lr] = av.z; As[lc + 3][lr] = av.w;
        Bs[lc + 0][lr] = bv.x; Bs[lc + 1][lr] = bv.y;
        Bs[lc + 2][lr] = bv.z; Bs[lc + 3][lr] = bv.w;
        __syncthreads();
#pragma unroll
        for (int kk = 0; kk < 8; kk++) {
            float ar[8];
            *(float4*)(ar)     = *(const float4*)&As[kk][ty * 8];
            *(float4*)(ar + 4) = *(const float4*)&As[kk][ty * 8 + 4];
            const ulonglong2 b01 = *(const ulonglong2*)&Bs[kk][tx * 8];
            const ulonglong2 b23 = *(const ulonglong2*)&Bs[kk][tx * 8 + 4];
#pragma unroll
            for (int i = 0; i < 8; i++) {
                const ull ap = dup2(ar[i]);
                acc2[i][0] = ffma2(ap, b01.x, acc2[i][0]);
                acc2[i][1] = ffma2(ap, b01.y, acc2[i][1]);
                acc2[i][2] = ffma2(ap, b23.x, acc2[i][2]);
                acc2[i][3] = ffma2(ap, b23.y, acc2[i][3]);
            }
        }
        __syncthreads();
    }

#pragma unroll
    for (int i = 0; i < 8; i++) {
        const size_t row = (size_t)(bm + ty * 8 + i);
        float out[8];
#pragma unroll
        for (int jp = 0; jp < 4; jp++)
            unpack2f(acc2[i][jp], out[2 * jp], out[2 * jp + 1]);
#pragma unroll
        for (int j = 0; j < 8; j++) {
            float bv = bias ? bias[bn + tx * 8 + j] : 0.0f;
            out[j] += bv;
        }
        float* cp = C + row * Nn + bn + tx * 8;
        *(float4*)(cp)     = *(const float4*)(out);
        *(float4*)(cp + 4) = *(const float4*)(out + 4);
    }
}

// ---------------- RoPE + split qkv -> q/k/v in [b][h][n][d] -----------------
__global__ void __launch_bounds__(512) rope_split()
{
    const int m = blockIdx.x;          // 0..4095
    const int b = m >> 11, n = m & (N_ - 1);
    const int h = threadIdx.x >> 5;
    const int i = threadIdx.x & 31;

    const float* row = g_qkv + (size_t)m * QKVN;
    const int c = h * D_;
    float q0 = row[c + i],            q1 = row[c + i + 32];
    float k0 = row[C_ + c + i],       k1 = row[C_ + c + i + 32];
    float v0 = row[2 * C_ + c + i],   v1 = row[2 * C_ + c + i + 32];

    float inv = exp2f(-11.0f * (float)i * (1.0f / 32.0f));  // 2048^(-i/32)
    float th = (float)n * inv;
    float cs = cosf(th), sn = sinf(th);

    size_t base = (((size_t)b * H_ + h) * N_ + n) * D_;
    g_q[base + i]      = q0 * cs - q1 * sn;
    g_q[base + i + 32] = q1 * cs + q0 * sn;
    g_k[base + i]      = k0 * cs - k1 * sn;
    g_k[base + i + 32] = k1 * cs + k0 * sn;
    g_v[base + i]      = v0;
    g_v[base + i + 32] = v1;
}

// ---------------- flash attention, fp32 + FFMA2, 128x64 tiles ---------------
// grid: (N/128, H, B), 256 threads = 16x16. Thread (tx,ty): rows ty*8..+7,
// cols tx*4..+3.  QK accumulators col-pair packed (f32x2); O likewise.
#define BQ   128
#define BKV  64
#define LDPS 68        // P row stride (row-major [128][68])

// smem float offsets
#define OFF_Q  0                       // Qs [128][64]
#define OFF_K  (OFF_Q + 128 * 64)      // Kt [64][64] xor-swizzled (d-major)
#define OFF_V  (OFF_K + 64 * 64)       // Vs [64][64] row-major (c-major)
#define OFF_P  (OFF_V + 64 * 64)       // Ps [128][68] row-major
#define OFF_MB (OFF_P + 128 * LDPS)    // mb [64]
#define SMEM_FLOATS (OFF_MB + 64)      // 25152 floats = 100608 B

extern __shared__ float sm_attn[];

__global__ void __launch_bounds__(256, 2) flash_attn(const int* __restrict__ kpm)
{
    float* Qs = sm_attn + OFF_Q;
    float* Kt = sm_attn + OFF_K;
    float* Vs = sm_attn + OFF_V;
    float* Ps = sm_attn + OFF_P;
    float* mb = sm_attn + OFF_MB;

    const int b = blockIdx.z, h = blockIdx.y;
    const int q0 = blockIdx.x * BQ;
    const int tid = threadIdx.x;
    const int tx = tid & 15, ty = tid >> 4;

    const size_t head_off = ((size_t)b * H_ + h) * N_ * D_;
    const float4* Qg4 = (const float4*)(g_q + head_off + (size_t)q0 * D_);
    const float4* Kg4 = (const float4*)(g_k + head_off);
    const float4* Vg4 = (const float4*)(g_v + head_off);

    // load Q tile (linear, coalesced)
    for (int i = tid; i < BQ * D_ / 4; i += 256)
        ((float4*)Qs)[i] = Qg4[i];

    float m_i[8], l_i[8];
    ull o2[8][2];                      // 8 rows x 2 col-pairs
#pragma unroll
    for (int ri = 0; ri < 8; ri++) {
        m_i[ri] = -INFINITY; l_i[ri] = 0.0f;
        o2[ri][0] = 0ull; o2[ri][1] = 0ull;
    }
    const float scale = 0.125f;        // 64^-0.5

    for (int kv0 = 0; kv0 < N_; kv0 += BKV) {
        __syncthreads();
        // K tile: transpose into Kt[d][c] with xor swizzle on the 16B granule
        for (int i4 = tid; i4 < BKV * D_ / 4; i4 += 256) {
            const int c = i4 >> 4, dg = i4 & 15;
            const float4 kv = Kg4[(kv0 + c) * 16 + dg];
            const float vals[4] = {kv.x, kv.y, kv.z, kv.w};
#pragma unroll
            for (int j = 0; j < 4; j++) {
                const int d = dg * 4 + j;
                Kt[(d << 6) + ((((c >> 2) ^ (d & 15))) << 2) + (c & 3)] = vals[j];
            }
        }
        // V tile (linear)
        for (int i4 = tid; i4 < BKV * D_ / 4; i4 += 256)
            ((float4*)Vs)[i4] = Vg4[kv0 * 16 + i4];
        if (tid < BKV)
            mb[tid] = (kpm[b * N_ + kv0 + tid] == 0) ? -1e9f : 0.0f;
        __syncthreads();

        // ---- S = Q K^T (col-pair packed) ----
        ull s2[8][2];
#pragma unroll
        for (int ri = 0; ri < 8; ri++) { s2[ri][0] = 0ull; s2[ri][1] = 0ull; }

#pragma unroll 4
        for (int kk2 = 0; kk2 < D_ / 2; kk2++) {
            float2 a2[8];
#pragma unroll
            for (int ri = 0; ri < 8; ri++)
                a2[ri] = *(const float2*)&Qs[((ty * 8 + ri) << 6) + kk2 * 2];
#pragma unroll
            for (int u = 0; u < 2; u++) {
                const int kk = kk2 * 2 + u;
                const ulonglong2 bb = *(const ulonglong2*)
                    &Kt[(kk << 6) + ((tx ^ (kk & 15)) << 2)];
#pragma unroll
                for (int ri = 0; ri < 8; ri++) {
                    const ull ap = dup2(u ? a2[ri].y : a2[ri].x);
                    s2[ri][0] = ffma2(ap, bb.x, s2[ri][0]);
                    s2[ri][1] = ffma2(ap, bb.y, s2[ri][1]);
                }
            }
        }

        // unpack, scale + mask bias
        float s[8][4];
#pragma unroll
        for (int ri = 0; ri < 8; ri++) {
            unpack2f(s2[ri][0], s[ri][0], s[ri][1]);
            unpack2f(s2[ri][1], s[ri][2], s[ri][3]);
        }
        float mbias[4];
#pragma unroll
        for (int cj = 0; cj < 4; cj++) mbias[cj] = mb[tx * 4 + cj];
#pragma unroll
        for (int ri = 0; ri < 8; ri++)
#pragma unroll
            for (int cj = 0; cj < 4; cj++)
                s[ri][cj] = fmaf(s[ri][cj], scale, mbias[cj]);

        // ---- online softmax ----
        float alpha[8];
#pragma unroll
        for (int ri = 0; ri < 8; ri++) {
            float mx = fmaxf(fmaxf(s[ri][0], s[ri][1]), fmaxf(s[ri][2], s[ri][3]));
#pragma unroll
            for (int off = 8; off >= 1; off >>= 1)
                mx = fmaxf(mx, __shfl_xor_sync(0xffffffffu, mx, off));
            const float mnew = fmaxf(m_i[ri], mx);
            alpha[ri] = __expf(m_i[ri] - mnew);
            m_i[ri] = mnew;
            float sum = 0.0f;
#pragma unroll
            for (int cj = 0; cj < 4; cj++) {
                s[ri][cj] = __expf(s[ri][cj] - mnew);
                sum += s[ri][cj];
            }
#pragma unroll
            for (int off = 8; off >= 1; off >>= 1)
                sum += __shfl_xor_sync(0xffffffffu, sum, off);
            l_i[ri] = l_i[ri] * alpha[ri] + sum;
        }
#pragma unroll
        for (int ri = 0; ri < 8; ri++) {
            const ull ad = dup2(alpha[ri]);
            o2[ri][0] = fmul2(ad, o2[ri][0]);
            o2[ri][1] = fmul2(ad, o2[ri][1]);
        }

        // stage P (row-major) then O += P @ V
#pragma unroll
        for (int ri = 0; ri < 8; ri++)
            *(float4*)&Ps[(ty * 8 + ri) * LDPS + tx * 4] = *(const float4*)&s[ri][0];
        __syncthreads();

#pragma unroll 4
        for (int c = 0; c < BKV; c++) {
            float p[8];
#pragma unroll
            for (int ri = 0; ri < 8; ri++)
                p[ri] = Ps[(ty * 8 + ri) * LDPS + c];
            const ulonglong2 vv = *(const ulonglong2*)&Vs[(c << 6) + (tx << 2)];
#pragma unroll
            for (int ri = 0; ri < 8; ri++) {
                const ull pd = dup2(p[ri]);
                o2[ri][0] = ffma2(pd, vv.x, o2[ri][0]);
                o2[ri][1] = ffma2(pd, vv.y, o2[ri][1]);
            }
        }
    }

    // write O / l  to g_ao[b][n][h*64 + d]
#pragma unroll
    for (int ri = 0; ri < 8; ri++) {
        const float linv = 1.0f / l_i[ri];
        const int n = q0 + ty * 8 + ri;
        float o[4];
        unpack2f(o2[ri][0], o[0], o[1]);
        unpack2f(o2[ri][1], o[2], o[3]);
#pragma unroll
        for (int cj = 0; cj < 4; cj++) o[cj] *= linv;
        float* op = g_ao + ((size_t)(b * N_ + n)) * C_ + h * D_ + tx * 4;
        *(float4*)op = *(const float4*)o;
    }
}

// ---------------------------------------------------------------------------
extern "C" void kernel_launch(void* const* d_in, const int* in_sizes, int n_in,
                              void* d_out, int out_size)
{
    const float* x      = (const float*)d_in[0];
    const float* w_qkv  = (const float*)d_in[1];
    const float* w_proj = (const float*)d_in[2];
    const float* b_proj = (const float*)d_in[3];
    const int*   kpm    = (const int*)d_in[4];
    float* out = (float*)d_out;

    float *qkv, *ao;
    cudaGetSymbolAddress((void**)&qkv, g_qkv);
    cudaGetSymbolAddress((void**)&ao, g_ao);

    // 1) qkv = x @ w_qkv^T
    sgemm_abt<<<dim3(QKVN / 128, M_ / 128), 256>>>(x, w_qkv, nullptr, qkv,
                                                   M_, QKVN, C_);
    // 2) split + RoPE -> g_q/g_k/g_v
    rope_split<<<M_, 512>>>();

    // 3) flash attention -> g_ao
    const int smem = SMEM_FLOATS * (int)sizeof(float);   // 100608 B
    cudaFuncSetAttribute(flash_attn, cudaFuncAttributeMaxDynamicSharedMemorySize, smem);
    flash_attn<<<dim3(N_ / BQ, H_, B_), 256, smem>>>(kpm);

    // 4) out = ao @ w_proj^T + b_proj
    sgemm_abt<<<dim3(C_ / 128, M_ / 128), 256>>>(ao, w_proj, b_proj, out,
                                                 M_, C_, C_);
}

// round 3
// speedup vs baseline: 1.0442x; 1.0043x over previous
#include <cuda_runtime.h>
#include <math.h>

#define B_   2
#define N_   2048
#define C_   1024
#define H_   16
#define D_   64
#define M_   (B_ * N_)      // 4096
#define QKVN 3072

typedef unsigned long long ull;

// ---------------- f32x2 packed-math helpers ---------------------------------
__device__ __forceinline__ ull dup2(float x) {
    ull d; asm("mov.b64 %0, {%1, %1};" : "=l"(d) : "f"(x)); return d;
}
__device__ __forceinline__ void unpack2f(ull v, float& lo, float& hi) {
    asm("mov.b64 {%0, %1}, %2;" : "=f"(lo), "=f"(hi) : "l"(v));
}
__device__ __forceinline__ ull ffma2(ull a, ull b, ull c) {
    ull d; asm("fma.rn.f32x2 %0, %1, %2, %3;" : "=l"(d) : "l"(a), "l"(b), "l"(c)); return d;
}
__device__ __forceinline__ ull fmul2(ull a, ull b) {
    ull d; asm("mul.rn.f32x2 %0, %1, %2;" : "=l"(d) : "l"(a), "l"(b)); return d;
}

// ---------------- scratch ----------------------------------------------------
__device__ float g_qkv[(size_t)M_ * QKVN];       // 48 MB
__device__ float g_q[(size_t)B_ * H_ * N_ * D_]; // 16 MB  [b][h][n][d]
__device__ float g_k[(size_t)B_ * H_ * N_ * D_];
__device__ float g_v[(size_t)B_ * H_ * N_ * D_];
__device__ float g_ao[(size_t)M_ * C_];          // 16 MB  [b][n][h*64+d]

// ---------------- generic C = A @ B^T (+bias) sgemm, 128x128x8 --------------
__global__ void __launch_bounds__(256) sgemm_abt(
    const float* __restrict__ A, const float* __restrict__ Bw,
    const float* __restrict__ bias, float* __restrict__ C,
    int M, int Nn, int K)
{
    __shared__ float As[8][128];
    __shared__ float Bs[8][128];
    const int tid = threadIdx.x;
    const int tx = tid & 15, ty = tid >> 4;
    const int bm = blockIdx.y << 7, bn = blockIdx.x << 7;
    const int lr = tid >> 1;
    const int lc = (tid & 1) << 2;
    const float* Ap = A  + (size_t)(bm + lr) * K + lc;
    const float* Bp = Bw + (size_t)(bn + lr) * K + lc;

    ull acc2[8][4];
#pragma unroll
    for (int i = 0; i < 8; i++)
#pragma unroll
        for (int jp = 0; jp < 4; jp++) acc2[i][jp] = 0ull;

    for (int k0 = 0; k0 < K; k0 += 8) {
        float4 av = *(const float4*)(Ap + k0);
        float4 bv = *(const float4*)(Bp + k0);
        As[lc + 0][lr] = av.x; As[lc + 1][lr] = av.y;
        As[lc + 2][lr] = av.z; As[lc + 3][lr] = av.w;
        Bs[lc + 0][lr] = bv.x; Bs[lc + 1][lr] = bv.y;
        Bs[lc + 2][lr] = bv.z; Bs[lc + 3][lr] = bv.w;
        __syncthreads();
#pragma unroll
        for (int kk = 0; kk < 8; kk++) {
            float ar[8];
            *(float4*)(ar)     = *(const float4*)&As[kk][ty * 8];
            *(float4*)(ar + 4) = *(const float4*)&As[kk][ty * 8 + 4];
            const ulonglong2 b01 = *(const ulonglong2*)&Bs[kk][tx * 8];
            const ulonglong2 b23 = *(const ulonglong2*)&Bs[kk][tx * 8 + 4];
#pragma unroll
            for (int i = 0; i < 8; i++) {
                const ull ap = dup2(ar[i]);
                acc2[i][0] = ffma2(ap, b01.x, acc2[i][0]);
                acc2[i][1] = ffma2(ap, b01.y, acc2[i][1]);
                acc2[i][2] = ffma2(ap, b23.x, acc2[i][2]);
                acc2[i][3] = ffma2(ap, b23.y, acc2[i][3]);
            }
        }
        __syncthreads();
    }

#pragma unroll
    for (int i = 0; i < 8; i++) {
        const size_t row = (size_t)(bm + ty * 8 + i);
        float out[8];
#pragma unroll
        for (int jp = 0; jp < 4; jp++)
            unpack2f(acc2[i][jp], out[2 * jp], out[2 * jp + 1]);
#pragma unroll
        for (int j = 0; j < 8; j++)
            out[j] += bias ? bias[bn + tx * 8 + j] : 0.0f;
        float* cp = C + row * Nn + bn + tx * 8;
        *(float4*)(cp)     = *(const float4*)(out);
        *(float4*)(cp + 4) = *(const float4*)(out + 4);
    }
}

// ---------------- RoPE + split qkv -> q/k/v in [b][h][n][d] -----------------
__global__ void __launch_bounds__(512) rope_split()
{
    const int m = blockIdx.x;
    const int b = m >> 11, n = m & (N_ - 1);
    const int h = threadIdx.x >> 5;
    const int i = threadIdx.x & 31;

    const float* row = g_qkv + (size_t)m * QKVN;
    const int c = h * D_;
    float q0 = row[c + i],            q1 = row[c + i + 32];
    float k0 = row[C_ + c + i],       k1 = row[C_ + c + i + 32];
    float v0 = row[2 * C_ + c + i],   v1 = row[2 * C_ + c + i + 32];

    float inv = exp2f(-11.0f * (float)i * (1.0f / 32.0f));  // 2048^(-i/32)
    float th = (float)n * inv;
    float cs = cosf(th), sn = sinf(th);

    size_t base = (((size_t)b * H_ + h) * N_ + n) * D_;
    g_q[base + i]      = q0 * cs - q1 * sn;
    g_q[base + i + 32] = q1 * cs + q0 * sn;
    g_k[base + i]      = k0 * cs - k1 * sn;
    g_k[base + i + 32] = k1 * cs + k0 * sn;
    g_v[base + i]      = v0;
    g_v[base + i + 32] = v1;
}

// ---------------- flash attention: 256x64 tiles, 8x8 per thread -------------
// 256 threads: tx = tid&7 (8 d-/kv-cols of 8), ty = tid>>3 (32 row-groups of 8).
// All operands staged transposed so inner loops are pure LDS.128 + FFMA2.
#define BQ    256
#define BKV   64
#define LDQ   264        // Qt/Pt row stride (BQ + 8)
#define LDK   68         // Kt/Vs row stride (BKV + 4)

#define OFF_QT 0                         // Qt [64][LDQ]
#define OFF_KT (OFF_QT + 64 * LDQ)       // Kt [64][LDK]
#define OFF_VS (OFF_KT + 64 * LDK)       // Vs [64][LDK]
#define OFF_PT (OFF_VS + 64 * LDK)       // Pt [64][LDQ]
#define OFF_MB (OFF_PT + 64 * LDQ)       // mb [64]
#define SMEM_FLOATS (OFF_MB + 64)        // 42560 floats = 170240 B

extern __shared__ float sm_attn[];

__global__ void __launch_bounds__(256, 1) flash_attn(const int* __restrict__ kpm)
{
    float* Qt = sm_attn + OFF_QT;
    float* Kt = sm_attn + OFF_KT;
    float* Vs = sm_attn + OFF_VS;
    float* Pt = sm_attn + OFF_PT;
    float* mb = sm_attn + OFF_MB;

    const int b = blockIdx.z, h = blockIdx.y;
    const int q0 = blockIdx.x * BQ;
    const int tid = threadIdx.x;
    const int tx = tid & 7, ty = tid >> 3;
    const int r0 = ty * 8;               // this thread's 8 rows
    const int c0 = tx * 8;               // this thread's 8 cols

    const size_t head_off = ((size_t)b * H_ + h) * N_ * D_;
    const float4* Qg4 = (const float4*)(g_q + head_off + (size_t)q0 * D_);
    const float4* Kg4 = (const float4*)(g_k + head_off);
    const float4* Vg4 = (const float4*)(g_v + head_off);

    // stage Q transposed: Qt[d][r]
    for (int i4 = tid; i4 < BQ * D_ / 4; i4 += 256) {
        const int r = i4 >> 4, dg = i4 & 15;
        const float4 qv = Qg4[i4];
        Qt[(dg * 4 + 0) * LDQ + r] = qv.x;
        Qt[(dg * 4 + 1) * LDQ + r] = qv.y;
        Qt[(dg * 4 + 2) * LDQ + r] = qv.z;
        Qt[(dg * 4 + 3) * LDQ + r] = qv.w;
    }

    float m_i[8], l_i[8];
    ull o2[8][4];
#pragma unroll
    for (int ri = 0; ri < 8; ri++) {
        m_i[ri] = -INFINITY; l_i[ri] = 0.0f;
#pragma unroll
        for (int jp = 0; jp < 4; jp++) o2[ri][jp] = 0ull;
    }
    const float scale = 0.125f;          // 64^-0.5

    for (int kv0 = 0; kv0 < N_; kv0 += BKV) {
        __syncthreads();
        // stage K transposed: Kt[d][c]; V direct: Vs[c][d]
        for (int i4 = tid; i4 < BKV * D_ / 4; i4 += 256) {
            const int c = i4 >> 4, dg = i4 & 15;
            const float4 kv = Kg4[(kv0 + c) * 16 + dg];
            Kt[(dg * 4 + 0) * LDK + c] = kv.x;
            Kt[(dg * 4 + 1) * LDK + c] = kv.y;
            Kt[(dg * 4 + 2) * LDK + c] = kv.z;
            Kt[(dg * 4 + 3) * LDK + c] = kv.w;
            const float4 vv = Vg4[(kv0 + c) * 16 + dg];
            *(float4*)&Vs[c * LDK + dg * 4] = vv;
        }
        if (tid < BKV)
            mb[tid] = (kpm[b * N_ + kv0 + tid] == 0) ? -1e9f : 0.0f;
        __syncthreads();

        // ---- S = Q K^T : 8 rows x 8 cols per thread, col-pair packed ----
        ull s2[8][4];
#pragma unroll
        for (int ri = 0; ri < 8; ri++)
#pragma unroll
            for (int jp = 0; jp < 4; jp++) s2[ri][jp] = 0ull;

#pragma unroll 8
        for (int kk = 0; kk < D_; kk++) {
            float a[8];
            *(float4*)(a)     = *(const float4*)&Qt[kk * LDQ + r0];
            *(float4*)(a + 4) = *(const float4*)&Qt[kk * LDQ + r0 + 4];
            const ulonglong2 b01 = *(const ulonglong2*)&Kt[kk * LDK + c0];
            const ulonglong2 b23 = *(const ulonglong2*)&Kt[kk * LDK + c0 + 4];
#pragma unroll
            for (int ri = 0; ri < 8; ri++) {
                const ull ap = dup2(a[ri]);
                s2[ri][0] = ffma2(ap, b01.x, s2[ri][0]);
                s2[ri][1] = ffma2(ap, b01.y, s2[ri][1]);
                s2[ri][2] = ffma2(ap, b23.x, s2[ri][2]);
                s2[ri][3] = ffma2(ap, b23.y, s2[ri][3]);
            }
        }

        // unpack, scale + mask bias
        float s[8][8];
#pragma unroll
        for (int ri = 0; ri < 8; ri++)
#pragma unroll
            for (int jp = 0; jp < 4; jp++)
                unpack2f(s2[ri][jp], s[ri][2 * jp], s[ri][2 * jp + 1]);
        float mbias[8];
#pragma unroll
        for (int cj = 0; cj < 8; cj++) mbias[cj] = mb[c0 + cj];
#pragma unroll
        for (int ri = 0; ri < 8; ri++)
#pragma unroll
            for (int cj = 0; cj < 8; cj++)
                s[ri][cj] = fmaf(s[ri][cj], scale, mbias[cj]);

        // ---- online softmax (row reduce over 8 tx lanes) ----
        float alpha[8];
#pragma unroll
        for (int ri = 0; ri < 8; ri++) {
            float mx = s[ri][0];
#pragma unroll
            for (int cj = 1; cj < 8; cj++) mx = fmaxf(mx, s[ri][cj]);
#pragma unroll
            for (int off = 4; off >= 1; off >>= 1)
                mx = fmaxf(mx, __shfl_xor_sync(0xffffffffu, mx, off));
            const float mnew = fmaxf(m_i[ri], mx);
            alpha[ri] = __expf(m_i[ri] - mnew);
            m_i[ri] = mnew;
            float sum = 0.0f;
#pragma unroll
            for (int cj = 0; cj < 8; cj++) {
                s[ri][cj] = __expf(s[ri][cj] - mnew);
                sum += s[ri][cj];
            }
#pragma unroll
            for (int off = 4; off >= 1; off >>= 1)
                sum += __shfl_xor_sync(0xffffffffu, sum, off);
            l_i[ri] = l_i[ri] * alpha[ri] + sum;
        }
#pragma unroll
        for (int ri = 0; ri < 8; ri++) {
            const ull ad = dup2(alpha[ri]);
#pragma unroll
            for (int jp = 0; jp < 4; jp++) o2[ri][jp] = fmul2(ad, o2[ri][jp]);
        }

        // stage P transposed: Pt[c][r]
#pragma unroll
        for (int cj = 0; cj < 8; cj++) {
            float4 f0 = make_float4(s[0][cj], s[1][cj], s[2][cj], s[3][cj]);
            float4 f1 = make_float4(s[4][cj], s[5][cj], s[6][cj], s[7][cj]);
            *(float4*)&Pt[(c0 + cj) * LDQ + r0]     = f0;
            *(float4*)&Pt[(c0 + cj) * LDQ + r0 + 4] = f1;
        }
        __syncthreads();

        // ---- O += P @ V ----
#pragma unroll 8
        for (int c = 0; c < BKV; c++) {
            float p[8];
            *(float4*)(p)     = *(const float4*)&Pt[c * LDQ + r0];
            *(float4*)(p + 4) = *(const float4*)&Pt[c * LDQ + r0 + 4];
            const ulonglong2 v01 = *(const ulonglong2*)&Vs[c * LDK + c0];
            const ulonglong2 v23 = *(const ulonglong2*)&Vs[c * LDK + c0 + 4];
#pragma unroll
            for (int ri = 0; ri < 8; ri++) {
                const ull pd = dup2(p[ri]);
                o2[ri][0] = ffma2(pd, v01.x, o2[ri][0]);
                o2[ri][1] = ffma2(pd, v01.y, o2[ri][1]);
                o2[ri][2] = ffma2(pd, v23.x, o2[ri][2]);
                o2[ri][3] = ffma2(pd, v23.y, o2[ri][3]);
            }
        }
    }

    // write O / l  to g_ao[b][n][h*64 + d]
#pragma unroll
    for (int ri = 0; ri < 8; ri++) {
        const float linv = 1.0f / l_i[ri];
        const int n = q0 + r0 + ri;
        float o[8];
#pragma unroll
        for (int jp = 0; jp < 4; jp++)
            unpack2f(o2[ri][jp], o[2 * jp], o[2 * jp + 1]);
#pragma unroll
        for (int cj = 0; cj < 8; cj++) o[cj] *= linv;
        float* op = g_ao + ((size_t)(b * N_ + n)) * C_ + h * D_ + c0;
        *(float4*)(op)     = *(const float4*)(o);
        *(float4*)(op + 4) = *(const float4*)(o + 4);
    }
}

// ---------------------------------------------------------------------------
extern "C" void kernel_launch(void* const* d_in, const int* in_sizes, int n_in,
                              void* d_out, int out_size)
{
    const float* x      = (const float*)d_in[0];
    const float* w_qkv  = (const float*)d_in[1];
    const float* w_proj = (const float*)d_in[2];
    const float* b_proj = (const float*)d_in[3];
    const int*   kpm    = (const int*)d_in[4];
    float* out = (float*)d_out;

    float *qkv, *ao;
    cudaGetSymbolAddress((void**)&qkv, g_qkv);
    cudaGetSymbolAddress((void**)&ao, g_ao);

    sgemm_abt<<<dim3(QKVN / 128, M_ / 128), 256>>>(x, w_qkv, nullptr, qkv,
                                                   M_, QKVN, C_);
    rope_split<<<M_, 512>>>();

    const int smem = SMEM_FLOATS * (int)sizeof(float);   // 170240 B
    cudaFuncSetAttribute(flash_attn, cudaFuncAttributeMaxDynamicSharedMemorySize, smem);
    flash_attn<<<dim3(N_ / BQ, H_, B_), 256, smem>>>(kpm);

    sgemm_abt<<<dim3(C_ / 128, M_ / 128), 256>>>(ao, w_proj, b_proj, out,
                                                 M_, C_, C_);
}

// round 6
// speedup vs baseline: 2.6712x; 2.5581x over previous
#include <cuda_runtime.h>
#include <cuda_bf16.h>
#include <math.h>
#include <stdint.h>

#define B_   2
#define N_   2048
#define C_   1024
#define H_   16
#define D_   64
#define M_   (B_ * N_)      // 4096
#define QKVN 3072

// ---------------- mma.sync / ldmatrix helpers (portable PTX) ----------------
__device__ __forceinline__ uint32_t smem_u32(const void* p) {
    uint32_t a;
    asm("{ .reg .u64 t; cvta.to.shared.u64 t, %1; cvt.u32.u64 %0, t; }"
        : "=r"(a) : "l"(p));
    return a;
}
__device__ __forceinline__ uint32_t swz(uint32_t off) {  // SW128: bits[6:4] ^= bits[9:7]
    return off ^ ((off >> 3) & 0x70);
}
__device__ __forceinline__ void ldsm4(uint32_t* r, uint32_t addr) {
    asm volatile("ldmatrix.sync.aligned.m8n8.x4.shared.b16 {%0,%1,%2,%3}, [%4];"
                 : "=r"(r[0]), "=r"(r[1]), "=r"(r[2]), "=r"(r[3]) : "r"(addr));
}
__device__ __forceinline__ void ldsm4t(uint32_t* r, uint32_t addr) {
    asm volatile("ldmatrix.sync.aligned.m8n8.x4.trans.shared.b16 {%0,%1,%2,%3}, [%4];"
                 : "=r"(r[0]), "=r"(r[1]), "=r"(r[2]), "=r"(r[3]) : "r"(addr));
}
__device__ __forceinline__ void mma16816(float* d, const uint32_t* a,
                                         uint32_t b0, uint32_t b1) {
    asm volatile(
        "mma.sync.aligned.m16n8k16.row.col.f32.bf16.bf16.f32 "
        "{%0,%1,%2,%3}, {%4,%5,%6,%7}, {%8,%9}, {%0,%1,%2,%3};"
        : "+f"(d[0]), "+f"(d[1]), "+f"(d[2]), "+f"(d[3])
        : "r"(a[0]), "r"(a[1]), "r"(a[2]), "r"(a[3]), "r"(b0), "r"(b1));
}
// split two floats into packed (hi, lo) bf16x2 words
__device__ __forceinline__ void splitpack(float x, float y, uint32_t& Hw, uint32_t& Lw) {
    __nv_bfloat16 hx = __float2bfloat16(x), hy = __float2bfloat16(y);
    __nv_bfloat16 lx = __float2bfloat16(x - __bfloat162float(hx));
    __nv_bfloat16 ly = __float2bfloat16(y - __bfloat162float(hy));
    Hw = (uint32_t)__bfloat16_as_ushort(hx) | ((uint32_t)__bfloat16_as_ushort(hy) << 16);
    Lw = (uint32_t)__bfloat16_as_ushort(lx) | ((uint32_t)__bfloat16_as_ushort(ly) << 16);
}

// ---------------- scratch ----------------------------------------------------
__device__ float g_qkv[(size_t)M_ * QKVN];                  // 48 MB
__device__ __nv_bfloat16 g_xh[(size_t)M_ * C_];
__device__ __nv_bfloat16 g_xl[(size_t)M_ * C_];
__device__ __nv_bfloat16 g_wqh[(size_t)QKVN * C_];
__device__ __nv_bfloat16 g_wql[(size_t)QKVN * C_];
__device__ __nv_bfloat16 g_wph[(size_t)C_ * C_];
__device__ __nv_bfloat16 g_wpl[(size_t)C_ * C_];
__device__ __nv_bfloat16 g_qh[(size_t)B_ * H_ * N_ * D_];   // per-head hi/lo
__device__ __nv_bfloat16 g_ql[(size_t)B_ * H_ * N_ * D_];
__device__ __nv_bfloat16 g_kh[(size_t)B_ * H_ * N_ * D_];
__device__ __nv_bfloat16 g_kl[(size_t)B_ * H_ * N_ * D_];
__device__ __nv_bfloat16 g_vh[(size_t)B_ * H_ * N_ * D_];
__device__ __nv_bfloat16 g_vl[(size_t)B_ * H_ * N_ * D_];
__device__ __nv_bfloat16 g_aoh[(size_t)M_ * C_];            // attn out hi/lo
__device__ __nv_bfloat16 g_aol[(size_t)M_ * C_];

extern __shared__ __align__(1024) char dyn_sm[];

// ---------------- fp32 -> (hi, lo) bf16 split --------------------------------
__global__ void __launch_bounds__(256) cvt_hilo(
    const float4* __restrict__ src, uint2* __restrict__ hi,
    uint2* __restrict__ lo, int n4)
{
    int i = blockIdx.x * 256 + threadIdx.x;
    if (i >= n4) return;
    float4 v = src[i];
    uint2 Hv, Lv;
    splitpack(v.x, v.y, Hv.x, Lv.x);
    splitpack(v.z, v.w, Hv.y, Lv.y);
    hi[i] = Hv;
    lo[i] = Lv;
}

// ---------------- GEMM: C = A @ B^T (+bias), bf16 hi/lo 3-pass mma ----------
// A: [M,1024] hi/lo bf16; B: [Nn,1024] hi/lo bf16. Block tile 128x128, kc=32.
// 8 warps: wm = w>>1 (4), wn = w&1 (2); warp tile 32(M) x 64(N).
// smem: [2 stages][4 ops][128 rows][32 bf16] = 64 KB, SW128 swizzle per 128B.
__global__ void __launch_bounds__(256, 1) gemm_mma(
    const __nv_bfloat16* __restrict__ Ah, const __nv_bfloat16* __restrict__ Al,
    const __nv_bfloat16* __restrict__ Bh, const __nv_bfloat16* __restrict__ Bl,
    const float* __restrict__ bias, float* __restrict__ C, int Nn)
{
    const int tid = threadIdx.x, lane = tid & 31, w = tid >> 5;
    const int wm = w >> 1, wn = w & 1;
    const int bm = blockIdx.y << 7, bn = blockIdx.x << 7;
    const uint32_t sb = smem_u32(dyn_sm);

    float acc[2][8][4];
#pragma unroll
    for (int mt = 0; mt < 2; mt++)
#pragma unroll
        for (int j = 0; j < 8; j++)
#pragma unroll
            for (int q = 0; q < 4; q++) acc[mt][j][q] = 0.0f;

    // ldmatrix per-lane byte offsets (add ks*32 per k16 step, then swizzle)
    uint32_t offA[2], offB[4];
#pragma unroll
    for (int mt = 0; mt < 2; mt++) {
        const int rowA = wm * 32 + mt * 16 + (lane & 15);
        offA[mt] = rowA * 64 + (lane >> 4) * 16;
    }
#pragma unroll
    for (int np = 0; np < 4; np++) {
        const int nB = wn * 64 + np * 16 + (lane & 7) + ((lane >> 4) << 3);
        offB[np] = nB * 64 + ((lane >> 3) & 1) * 16;
    }

    const __nv_bfloat16* srcs[4] = {Ah, Al, Bh, Bl};
    uint4 ldr[8];

    auto load_chunk = [&](int c) {
#pragma unroll
        for (int i = 0; i < 8; i++) {
            const int gid = tid + i * 256;
            const int op = gid >> 9, g = gid & 511;
            const int row = g >> 2, kg = g & 3;
            const int rb = (op < 2) ? bm : bn;
            ldr[i] = *(const uint4*)(srcs[op] + (size_t)(rb + row) * C_
                                     + c * 32 + kg * 8);
        }
    };
    auto store_chunk = [&](int st) {
        char* base = dyn_sm + st * 32768;
#pragma unroll
        for (int i = 0; i < 8; i++) {
            const int gid = tid + i * 256;
            const int op = gid >> 9, g = gid & 511;
            const int row = g >> 2, kg = g & 3;
            *(uint4*)(base + op * 8192 + swz(row * 64 + kg * 16)) = ldr[i];
        }
    };

    load_chunk(0);
    store_chunk(0);

    for (int c = 0; c < 32; c++) {
        __syncthreads();
        if (c + 1 < 32) load_chunk(c + 1);
        const uint32_t stb = sb + (c & 1) * 32768;
#pragma unroll
        for (int ks = 0; ks < 2; ks++) {
            uint32_t a_h[2][4], a_l[2][4];
#pragma unroll
            for (int mt = 0; mt < 2; mt++) {
                ldsm4(a_h[mt], stb + swz(offA[mt] + ks * 32));
                ldsm4(a_l[mt], stb + 8192 + swz(offA[mt] + ks * 32));
            }
#pragma unroll
            for (int np = 0; np < 4; np++) {
                uint32_t b_h[4], b_l[4];
                ldsm4(b_h, stb + 16384 + swz(offB[np] + ks * 32));
                ldsm4(b_l, stb + 24576 + swz(offB[np] + ks * 32));
#pragma unroll
                for (int mt = 0; mt < 2; mt++) {
                    mma16816(acc[mt][2 * np],     a_h[mt], b_h[0], b_h[1]);
                    mma16816(acc[mt][2 * np + 1], a_h[mt], b_h[2], b_h[3]);
                    mma16816(acc[mt][2 * np],     a_h[mt], b_l[0], b_l[1]);
                    mma16816(acc[mt][2 * np + 1], a_h[mt], b_l[2], b_l[3]);
                    mma16816(acc[mt][2 * np],     a_l[mt], b_h[0], b_h[1]);
                    mma16816(acc[mt][2 * np + 1], a_l[mt], b_h[2], b_h[3]);
                }
            }
        }
        if (c + 1 < 32) { __syncthreads(); store_chunk((c + 1) & 1); }
    }

#pragma unroll
    for (int mt = 0; mt < 2; mt++)
#pragma unroll
        for (int j = 0; j < 8; j++) {
            const int row = bm + wm * 32 + mt * 16 + (lane >> 2);
            const int col = bn + wn * 64 + j * 8 + ((lane & 3) << 1);
            const float b0 = bias ? bias[col] : 0.0f;
            const float b1 = bias ? bias[col + 1] : 0.0f;
            float2 v0 = make_float2(acc[mt][j][0] + b0, acc[mt][j][1] + b1);
            float2 v1 = make_float2(acc[mt][j][2] + b0, acc[mt][j][3] + b1);
            *(float2*)(C + (size_t)row * Nn + col) = v0;
            *(float2*)(C + (size_t)(row + 8) * Nn + col) = v1;
        }
}

// ---------------- RoPE + split -> q/k/v hi/lo bf16 [b][h][n][d] -------------
__global__ void __launch_bounds__(512) rope_split()
{
    const int m = blockIdx.x;
    const int b = m >> 11, n = m & (N_ - 1);
    const int h = threadIdx.x >> 5;
    const int i = threadIdx.x & 31;

    const float* row = g_qkv + (size_t)m * QKVN;
    const int c = h * D_;
    float q0 = row[c + i],            q1 = row[c + i + 32];
    float k0 = row[C_ + c + i],       k1 = row[C_ + c + i + 32];
    float v0 = row[2 * C_ + c + i],   v1 = row[2 * C_ + c + i + 32];

    float inv = exp2f(-11.0f * (float)i * (1.0f / 32.0f));  // 2048^(-i/32)
    float th = (float)n * inv;
    float cs = cosf(th), sn = sinf(th);

    float qa = q0 * cs - q1 * sn, qb = q1 * cs + q0 * sn;
    float ka = k0 * cs - k1 * sn, kb = k1 * cs + k0 * sn;

    size_t base = (((size_t)b * H_ + h) * N_ + n) * D_;
    const float vals[6] = {qa, qb, ka, kb, v0, v1};
    __nv_bfloat16* Hp[6] = {g_qh + base + i, g_qh + base + i + 32,
                            g_kh + base + i, g_kh + base + i + 32,
                            g_vh + base + i, g_vh + base + i + 32};
    __nv_bfloat16* Lp[6] = {g_ql + base + i, g_ql + base + i + 32,
                            g_kl + base + i, g_kl + base + i + 32,
                            g_vl + base + i, g_vl + base + i + 32};
#pragma unroll
    for (int t = 0; t < 6; t++) {
        __nv_bfloat16 hv = __float2bfloat16(vals[t]);
        *Hp[t] = hv;
        *Lp[t] = __float2bfloat16(vals[t] - __bfloat162float(hv));
    }
}

// ---------------- flash attention with mma.sync, BQ=128 BKV=64 --------------
// 8 warps, each owns 16 q-rows. Q frags preloaded; K non-trans B operand;
// V via ldmatrix.trans; P re-packed register-direct from S fragments.
// smem bytes: Qh 0, Ql 16384, Kh 32768, Kl 40960, Vh 49152, Vl 57344, mb 65536.
#define AT_SMEM (65536 + 256)

__global__ void __launch_bounds__(256, 1) flash_attn_mma(const int* __restrict__ kpm)
{
    const int tid = threadIdx.x, lane = tid & 31, w = tid >> 5;
    const int b = blockIdx.z, h = blockIdx.y;
    const int q0 = blockIdx.x << 7;
    const uint32_t sb = smem_u32(dyn_sm);
    const size_t hoff = ((size_t)b * H_ + h) * N_ * D_;
    float* mb = (float*)(dyn_sm + 65536);

    // stage Q hi/lo [128][64]
    {
        const __nv_bfloat16* qsrc[2] = {g_qh + hoff + (size_t)q0 * D_,
                                        g_ql + hoff + (size_t)q0 * D_};
#pragma unroll
        for (int i = 0; i < 8; i++) {
            const int gid = tid + i * 256;         // 2048 granules
            const int op = gid >> 10, g = gid & 1023;
            const int row = g >> 3, dg = g & 7;
            uint4 v = *(const uint4*)(qsrc[op] + row * 64 + dg * 8);
            *(uint4*)(dyn_sm + op * 16384 + swz(row * 128 + dg * 16)) = v;
        }
    }
    __syncthreads();

    // preload Q fragments (k = d, 4 k16 steps)
    uint32_t qfh[4][4], qfl[4][4];
    {
        const int rowQ = w * 16 + (lane & 15);
        const uint32_t base = rowQ * 128 + (lane >> 4) * 16;
#pragma unroll
        for (int ks = 0; ks < 4; ks++) {
            ldsm4(qfh[ks], sb + swz(base + ks * 32));
            ldsm4(qfl[ks], sb + 16384 + swz(base + ks * 32));
        }
    }

    float o[8][4];
#pragma unroll
    for (int j = 0; j < 8; j++)
#pragma unroll
        for (int q = 0; q < 4; q++) o[j][q] = 0.0f;
    float m0 = -INFINITY, m1 = -INFINITY, l0 = 0.0f, l1 = 0.0f;

    const __nv_bfloat16* ksrc[4] = {g_kh + hoff, g_kl + hoff, g_vh + hoff, g_vl + hoff};

    for (int kv0 = 0; kv0 < N_; kv0 += 64) {
        __syncthreads();
#pragma unroll
        for (int i = 0; i < 8; i++) {
            const int gid = tid + i * 256;          // 2048 granules
            const int op = gid >> 9, g = gid & 511;
            const int row = g >> 3, dg = g & 7;
            uint4 v = *(const uint4*)(ksrc[op] + (size_t)(kv0 + row) * 64 + dg * 8);
            *(uint4*)(dyn_sm + 32768 + op * 8192 + swz(row * 128 + dg * 16)) = v;
        }
        if (tid < 64)
            mb[tid] = (kpm[b * N_ + kv0 + tid] == 0) ? -1e9f : 0.0f;
        __syncthreads();

        // ---- S = Q K^T (3-pass hi/lo) ----
        float s[8][4];
#pragma unroll
        for (int j = 0; j < 8; j++)
#pragma unroll
            for (int q = 0; q < 4; q++) s[j][q] = 0.0f;

#pragma unroll
        for (int ks = 0; ks < 4; ks++) {
#pragma unroll
            for (int np = 0; np < 4; np++) {
                const int nB = np * 16 + (lane & 7) + ((lane >> 4) << 3);
                const uint32_t ob = nB * 128 + ((lane >> 3) & 1) * 16 + ks * 32;
                uint32_t kb_h[4], kb_l[4];
                ldsm4(kb_h, sb + 32768 + swz(ob));
                ldsm4(kb_l, sb + 40960 + swz(ob));
                mma16816(s[2 * np],     qfh[ks], kb_h[0], kb_h[1]);
                mma16816(s[2 * np + 1], qfh[ks], kb_h[2], kb_h[3]);
                mma16816(s[2 * np],     qfh[ks], kb_l[0], kb_l[1]);
                mma16816(s[2 * np + 1], qfh[ks], kb_l[2], kb_l[3]);
                mma16816(s[2 * np],     qfl[ks], kb_h[0], kb_h[1]);
                mma16816(s[2 * np + 1], qfl[ks], kb_h[2], kb_h[3]);
            }
        }

        // ---- scale + mask + online softmax ----
        const float scale = 0.125f;
        float mx0 = -INFINITY, mx1 = -INFINITY;
#pragma unroll
        for (int j = 0; j < 8; j++) {
            const int col = j * 8 + ((lane & 3) << 1);
            const float mb0 = mb[col], mb1 = mb[col + 1];
            s[j][0] = fmaf(s[j][0], scale, mb0);
            s[j][1] = fmaf(s[j][1], scale, mb1);
            s[j][2] = fmaf(s[j][2], scale, mb0);
            s[j][3] = fmaf(s[j][3], scale, mb1);
            mx0 = fmaxf(mx0, fmaxf(s[j][0], s[j][1]));
            mx1 = fmaxf(mx1, fmaxf(s[j][2], s[j][3]));
        }
        mx0 = fmaxf(mx0, __shfl_xor_sync(0xffffffffu, mx0, 1));
        mx0 = fmaxf(mx0, __shfl_xor_sync(0xffffffffu, mx0, 2));
        mx1 = fmaxf(mx1, __shfl_xor_sync(0xffffffffu, mx1, 1));
        mx1 = fmaxf(mx1, __shfl_xor_sync(0xffffffffu, mx1, 2));
        const float mn0 = fmaxf(m0, mx0), mn1 = fmaxf(m1, mx1);
        const float a0 = __expf(m0 - mn0), a1 = __expf(m1 - mn1);
        m0 = mn0; m1 = mn1;
        float s0 = 0.0f, s1 = 0.0f;
#pragma unroll
        for (int j = 0; j < 8; j++) {
            s[j][0] = __expf(s[j][0] - mn0);
            s[j][1] = __expf(s[j][1] - mn0);
            s[j][2] = __expf(s[j][2] - mn1);
            s[j][3] = __expf(s[j][3] - mn1);
            s0 += s[j][0] + s[j][1];
            s1 += s[j][2] + s[j][3];
        }
        s0 += __shfl_xor_sync(0xffffffffu, s0, 1);
        s0 += __shfl_xor_sync(0xffffffffu, s0, 2);
        s1 += __shfl_xor_sync(0xffffffffu, s1, 1);
        s1 += __shfl_xor_sync(0xffffffffu, s1, 2);
        l0 = l0 * a0 + s0;
        l1 = l1 * a1 + s1;
#pragma unroll
        for (int j = 0; j < 8; j++) {
            o[j][0] *= a0; o[j][1] *= a0;
            o[j][2] *= a1; o[j][3] *= a1;
        }

        // ---- pack P fragments (hi/lo) straight from S registers ----
        uint32_t ph[4][4], pl[4][4];
#pragma unroll
        for (int kt = 0; kt < 4; kt++) {
            const int t0 = 2 * kt, t1 = 2 * kt + 1;
            splitpack(s[t0][0], s[t0][1], ph[kt][0], pl[kt][0]);
            splitpack(s[t0][2], s[t0][3], ph[kt][1], pl[kt][1]);
            splitpack(s[t1][0], s[t1][1], ph[kt][2], pl[kt][2]);
            splitpack(s[t1][2], s[t1][3], ph[kt][3], pl[kt][3]);
        }

        // ---- O += P @ V (3-pass hi/lo), V via ldmatrix.trans ----
#pragma unroll
        for (int kt = 0; kt < 4; kt++) {
#pragma unroll
            for (int dp = 0; dp < 4; dp++) {
                const int kvr = kt * 16 + (lane & 15);
                const uint32_t ob = kvr * 128 + (dp * 2 + (lane >> 4)) * 16;
                uint32_t v_h[4], v_l[4];
                ldsm4t(v_h, sb + 49152 + swz(ob));
                ldsm4t(v_l, sb + 57344 + swz(ob));
                mma16816(o[2 * dp],     ph[kt], v_h[0], v_h[1]);
                mma16816(o[2 * dp + 1], ph[kt], v_h[2], v_h[3]);
                mma16816(o[2 * dp],     ph[kt], v_l[0], v_l[1]);
                mma16816(o[2 * dp + 1], ph[kt], v_l[2], v_l[3]);
                mma16816(o[2 * dp],     pl[kt], v_h[0], v_h[1]);
                mma16816(o[2 * dp + 1], pl[kt], v_h[2], v_h[3]);
            }
        }
    }

    // ---- normalize + hi/lo split -> g_aoh/g_aol [b][n][h*64+d] ----
    const float li0 = 1.0f / l0, li1 = 1.0f / l1;
    const int n0 = q0 + w * 16 + (lane >> 2);
    const size_t ro0 = (size_t)(b * N_ + n0) * C_ + h * D_;
    const size_t ro1 = ro0 + (size_t)8 * C_;
#pragma unroll
    for (int j = 0; j < 8; j++) {
        const int col = j * 8 + ((lane & 3) << 1);
        uint32_t Hw, Lw;
        splitpack(o[j][0] * li0, o[j][1] * li0, Hw, Lw);
        *(uint32_t*)(g_aoh + ro0 + col) = Hw;
        *(uint32_t*)(g_aol + ro0 + col) = Lw;
        splitpack(o[j][2] * li1, o[j][3] * li1, Hw, Lw);
        *(uint32_t*)(g_aoh + ro1 + col) = Hw;
        *(uint32_t*)(g_aol + ro1 + col) = Lw;
    }
}

// ---------------------------------------------------------------------------
extern "C" void kernel_launch(void* const* d_in, const int* in_sizes, int n_in,
                              void* d_out, int out_size)
{
    const float* x      = (const float*)d_in[0];
    const float* w_qkv  = (const float*)d_in[1];
    const float* w_proj = (const float*)d_in[2];
    const float* b_proj = (const float*)d_in[3];
    const int*   kpm    = (const int*)d_in[4];
    float* out = (float*)d_out;

    float* qkv;
    __nv_bfloat16 *xh, *xl, *wqh, *wql, *wph, *wpl, *aoh, *aol;
    cudaGetSymbolAddress((void**)&qkv, g_qkv);
    cudaGetSymbolAddress((void**)&xh,  g_xh);
    cudaGetSymbolAddress((void**)&xl,  g_xl);
    cudaGetSymbolAddress((void**)&wqh, g_wqh);
    cudaGetSymbolAddress((void**)&wql, g_wql);
    cudaGetSymbolAddress((void**)&wph, g_wph);
    cudaGetSymbolAddress((void**)&wpl, g_wpl);
    cudaGetSymbolAddress((void**)&aoh, g_aoh);
    cudaGetSymbolAddress((void**)&aol, g_aol);

    // 0) split fp32 -> bf16 hi/lo
    cvt_hilo<<<(M_ * C_ / 4 + 255) / 256, 256>>>(
        (const float4*)x, (uint2*)xh, (uint2*)xl, M_ * C_ / 4);
    cvt_hilo<<<(QKVN * C_ / 4 + 255) / 256, 256>>>(
        (const float4*)w_qkv, (uint2*)wqh, (uint2*)wql, QKVN * C_ / 4);
    cvt_hilo<<<(C_ * C_ / 4 + 255) / 256, 256>>>(
        (const float4*)w_proj, (uint2*)wph, (uint2*)wpl, C_ * C_ / 4);

    // 1) qkv = x @ w_qkv^T (mma.sync bf16 3-pass)
    cudaFuncSetAttribute(gemm_mma, cudaFuncAttributeMaxDynamicSharedMemorySize, 65536);
    gemm_mma<<<dim3(QKVN / 128, M_ / 128), 256, 65536>>>(
        xh, xl, wqh, wql, nullptr, qkv, QKVN);

    // 2) RoPE + split -> per-head hi/lo bf16
    rope_split<<<M_, 512>>>();

    // 3) flash attention (mma.sync) -> g_aoh/g_aol
    cudaFuncSetAttribute(flash_attn_mma, cudaFuncAttributeMaxDynamicSharedMemorySize,
                         AT_SMEM);
    flash_attn_mma<<<dim3(N_ / 128, H_, B_), 256, AT_SMEM>>>(kpm);

    // 4) out = ao @ w_proj^T + b_proj
    gemm_mma<<<dim3(C_ / 128, M_ / 128), 256, 65536>>>(
        aoh, aol, wph, wpl, b_proj, out, C_);
}

// round 7
// speedup vs baseline: 3.0728x; 1.1503x over previous
#include <cuda_runtime.h>
#include <cuda_bf16.h>
#include <math.h>
#include <stdint.h>

#define B_   2
#define N_   2048
#define C_   1024
#define H_   16
#define D_   64
#define M_   (B_ * N_)      // 4096
#define QKVN 3072

// ---------------- mma.sync / ldmatrix helpers (portable PTX) ----------------
__device__ __forceinline__ uint32_t smem_u32(const void* p) {
    uint32_t a;
    asm("{ .reg .u64 t; cvta.to.shared.u64 t, %1; cvt.u32.u64 %0, t; }"
        : "=r"(a) : "l"(p));
    return a;
}
__device__ __forceinline__ uint32_t swz(uint32_t off) {  // SW128: bits[6:4] ^= bits[9:7]
    return off ^ ((off >> 3) & 0x70);
}
__device__ __forceinline__ void ldsm4(uint32_t* r, uint32_t addr) {
    asm volatile("ldmatrix.sync.aligned.m8n8.x4.shared.b16 {%0,%1,%2,%3}, [%4];"
                 : "=r"(r[0]), "=r"(r[1]), "=r"(r[2]), "=r"(r[3]) : "r"(addr));
}
__device__ __forceinline__ void ldsm4t(uint32_t* r, uint32_t addr) {
    asm volatile("ldmatrix.sync.aligned.m8n8.x4.trans.shared.b16 {%0,%1,%2,%3}, [%4];"
                 : "=r"(r[0]), "=r"(r[1]), "=r"(r[2]), "=r"(r[3]) : "r"(addr));
}
__device__ __forceinline__ void mma16816(float* d, const uint32_t* a,
                                         uint32_t b0, uint32_t b1) {
    asm volatile(
        "mma.sync.aligned.m16n8k16.row.col.f32.bf16.bf16.f32 "
        "{%0,%1,%2,%3}, {%4,%5,%6,%7}, {%8,%9}, {%0,%1,%2,%3};"
        : "+f"(d[0]), "+f"(d[1]), "+f"(d[2]), "+f"(d[3])
        : "r"(a[0]), "r"(a[1]), "r"(a[2]), "r"(a[3]), "r"(b0), "r"(b1));
}
__device__ __forceinline__ void cp16(uint32_t sdst, const void* gsrc) {
    asm volatile("cp.async.cg.shared.global [%0], [%1], 16;"
                 :: "r"(sdst), "l"(gsrc) : "memory");
}
#define CP_COMMIT() asm volatile("cp.async.commit_group;" ::: "memory")
#define CP_WAIT(n)  asm volatile("cp.async.wait_group %0;" :: "n"(n) : "memory")

// split two floats into packed (hi, lo) bf16x2 words
__device__ __forceinline__ void splitpack(float x, float y, uint32_t& Hw, uint32_t& Lw) {
    __nv_bfloat16 hx = __float2bfloat16(x), hy = __float2bfloat16(y);
    __nv_bfloat16 lx = __float2bfloat16(x - __bfloat162float(hx));
    __nv_bfloat16 ly = __float2bfloat16(y - __bfloat162float(hy));
    Hw = (uint32_t)__bfloat16_as_ushort(hx) | ((uint32_t)__bfloat16_as_ushort(hy) << 16);
    Lw = (uint32_t)__bfloat16_as_ushort(lx) | ((uint32_t)__bfloat16_as_ushort(ly) << 16);
}

// ---------------- scratch ----------------------------------------------------
__device__ float g_qkv[(size_t)M_ * QKVN];                  // 48 MB
__device__ __nv_bfloat16 g_xh[(size_t)M_ * C_];
__device__ __nv_bfloat16 g_xl[(size_t)M_ * C_];
__device__ __nv_bfloat16 g_wqh[(size_t)QKVN * C_];
__device__ __nv_bfloat16 g_wql[(size_t)QKVN * C_];
__device__ __nv_bfloat16 g_wph[(size_t)C_ * C_];
__device__ __nv_bfloat16 g_wpl[(size_t)C_ * C_];
__device__ __nv_bfloat16 g_qh[(size_t)B_ * H_ * N_ * D_];
__device__ __nv_bfloat16 g_ql[(size_t)B_ * H_ * N_ * D_];
__device__ __nv_bfloat16 g_kh[(size_t)B_ * H_ * N_ * D_];
__device__ __nv_bfloat16 g_kl[(size_t)B_ * H_ * N_ * D_];
__device__ __nv_bfloat16 g_vh[(size_t)B_ * H_ * N_ * D_];
__device__ __nv_bfloat16 g_vl[(size_t)B_ * H_ * N_ * D_];
__device__ __nv_bfloat16 g_aoh[(size_t)M_ * C_];
__device__ __nv_bfloat16 g_aol[(size_t)M_ * C_];

extern __shared__ __align__(1024) char dyn_sm[];

// ---------------- fp32 -> (hi, lo) bf16 split --------------------------------
__global__ void __launch_bounds__(256) cvt_hilo(
    const float4* __restrict__ src, uint2* __restrict__ hi,
    uint2* __restrict__ lo, int n4)
{
    int i = blockIdx.x * 256 + threadIdx.x;
    if (i >= n4) return;
    float4 v = src[i];
    uint2 Hv, Lv;
    splitpack(v.x, v.y, Hv.x, Lv.x);
    splitpack(v.z, v.w, Hv.y, Lv.y);
    hi[i] = Hv;
    lo[i] = Lv;
}

// ---------------- GEMM: C = A @ B^T (+bias), bf16 hi/lo 3-pass mma ----------
// cp.async 4-stage pipeline. Block tile 128x128, kc=32, stage=32KB (4 ops).
#define G_STAGE 32768
#define G_SMEM  (4 * G_STAGE)          // 131072

__global__ void __launch_bounds__(256, 1) gemm_mma(
    const __nv_bfloat16* __restrict__ Ah, const __nv_bfloat16* __restrict__ Al,
    const __nv_bfloat16* __restrict__ Bh, const __nv_bfloat16* __restrict__ Bl,
    const float* __restrict__ bias, float* __restrict__ C, int Nn)
{
    const int tid = threadIdx.x, lane = tid & 31, w = tid >> 5;
    const int wm = w >> 1, wn = w & 1;
    const int bm = blockIdx.y << 7, bn = blockIdx.x << 7;
    const uint32_t sb = smem_u32(dyn_sm);

    float acc[2][8][4];
#pragma unroll
    for (int mt = 0; mt < 2; mt++)
#pragma unroll
        for (int j = 0; j < 8; j++)
#pragma unroll
            for (int q = 0; q < 4; q++) acc[mt][j][q] = 0.0f;

    // ldmatrix per-lane byte offsets within a stage
    uint32_t offA[2], offB[4];
#pragma unroll
    for (int mt = 0; mt < 2; mt++) {
        const int rowA = wm * 32 + mt * 16 + (lane & 15);
        offA[mt] = rowA * 64 + (lane >> 4) * 16;
    }
#pragma unroll
    for (int np = 0; np < 4; np++) {
        const int nB = wn * 64 + np * 16 + (lane & 7) + ((lane >> 4) << 3);
        offB[np] = nB * 64 + ((lane >> 3) & 1) * 16;
    }

    // cp.async per-thread src/dst precompute (8 granules of 16B per stage)
    const __nv_bfloat16* srcs[4] = {Ah, Al, Bh, Bl};
    const __nv_bfloat16* gsrc[8];
    uint32_t sdst[8];
#pragma unroll
    for (int i = 0; i < 8; i++) {
        const int gid = tid + i * 256;
        const int op = gid >> 9, g = gid & 511;
        const int row = g >> 2, kg = g & 3;
        const int rb = (op < 2) ? bm : bn;
        gsrc[i] = srcs[op] + (size_t)(rb + row) * C_ + kg * 8;
        sdst[i] = op * 8192 + swz(row * 64 + kg * 16);
    }

    auto issue = [&](int c) {
        const uint32_t stb = sb + (c & 3) * G_STAGE;
#pragma unroll
        for (int i = 0; i < 8; i++)
            cp16(stb + sdst[i], gsrc[i] + c * 32);
    };

    issue(0); CP_COMMIT();
    issue(1); CP_COMMIT();
    issue(2); CP_COMMIT();

    for (int c = 0; c < 32; c++) {
        CP_WAIT(2);
        __syncthreads();
        if (c + 3 < 32) issue(c + 3);
        CP_COMMIT();

        const uint32_t stb = sb + (c & 3) * G_STAGE;
#pragma unroll
        for (int ks = 0; ks < 2; ks++) {
            uint32_t a_h[2][4], a_l[2][4];
#pragma unroll
            for (int mt = 0; mt < 2; mt++) {
                ldsm4(a_h[mt], stb + swz(offA[mt] + ks * 32));
                ldsm4(a_l[mt], stb + 8192 + swz(offA[mt] + ks * 32));
            }
#pragma unroll
            for (int np = 0; np < 4; np++) {
                uint32_t b_h[4], b_l[4];
                ldsm4(b_h, stb + 16384 + swz(offB[np] + ks * 32));
                ldsm4(b_l, stb + 24576 + swz(offB[np] + ks * 32));
#pragma unroll
                for (int mt = 0; mt < 2; mt++) {
                    mma16816(acc[mt][2 * np],     a_h[mt], b_h[0], b_h[1]);
                    mma16816(acc[mt][2 * np + 1], a_h[mt], b_h[2], b_h[3]);
                    mma16816(acc[mt][2 * np],     a_h[mt], b_l[0], b_l[1]);
                    mma16816(acc[mt][2 * np + 1], a_h[mt], b_l[2], b_l[3]);
                    mma16816(acc[mt][2 * np],     a_l[mt], b_h[0], b_h[1]);
                    mma16816(acc[mt][2 * np + 1], a_l[mt], b_h[2], b_h[3]);
                }
            }
        }
    }

#pragma unroll
    for (int mt = 0; mt < 2; mt++)
#pragma unroll
        for (int j = 0; j < 8; j++) {
            const int row = bm + wm * 32 + mt * 16 + (lane >> 2);
            const int col = bn + wn * 64 + j * 8 + ((lane & 3) << 1);
            const float b0 = bias ? bias[col] : 0.0f;
            const float b1 = bias ? bias[col + 1] : 0.0f;
            float2 v0 = make_float2(acc[mt][j][0] + b0, acc[mt][j][1] + b1);
            float2 v1 = make_float2(acc[mt][j][2] + b0, acc[mt][j][3] + b1);
            *(float2*)(C + (size_t)row * Nn + col) = v0;
            *(float2*)(C + (size_t)(row + 8) * Nn + col) = v1;
        }
}

// ---------------- RoPE + split -> q/k/v hi/lo bf16 [b][h][n][d] -------------
__global__ void __launch_bounds__(512) rope_split()
{
    const int m = blockIdx.x;
    const int b = m >> 11, n = m & (N_ - 1);
    const int h = threadIdx.x >> 5;
    const int i = threadIdx.x & 31;

    const float* row = g_qkv + (size_t)m * QKVN;
    const int c = h * D_;
    float q0 = row[c + i],            q1 = row[c + i + 32];
    float k0 = row[C_ + c + i],       k1 = row[C_ + c + i + 32];
    float v0 = row[2 * C_ + c + i],   v1 = row[2 * C_ + c + i + 32];

    float inv = exp2f(-11.0f * (float)i * (1.0f / 32.0f));  // 2048^(-i/32)
    float th = (float)n * inv;
    float cs = cosf(th), sn = sinf(th);

    float qa = q0 * cs - q1 * sn, qb = q1 * cs + q0 * sn;
    float ka = k0 * cs - k1 * sn, kb = k1 * cs + k0 * sn;

    size_t base = (((size_t)b * H_ + h) * N_ + n) * D_;
    const float vals[6] = {qa, qb, ka, kb, v0, v1};
    __nv_bfloat16* Hp[6] = {g_qh + base + i, g_qh + base + i + 32,
                            g_kh + base + i, g_kh + base + i + 32,
                            g_vh + base + i, g_vh + base + i + 32};
    __nv_bfloat16* Lp[6] = {g_ql + base + i, g_ql + base + i + 32,
                            g_kl + base + i, g_kl + base + i + 32,
                            g_vl + base + i, g_vl + base + i + 32};
#pragma unroll
    for (int t = 0; t < 6; t++) {
        __nv_bfloat16 hv = __float2bfloat16(vals[t]);
        *Hp[t] = hv;
        *Lp[t] = __float2bfloat16(vals[t] - __bfloat162float(hv));
    }
}

// ---------------- flash attention with mma.sync, BQ=128 BKV=64 --------------
// cp.async double-buffered K/V stages (32KB each).
// smem: Qh 0, Ql 16384, KV stage0 @32768, stage1 @65536 (Kh,Kl,Vh,Vl 8KB each),
// mb[2][64] @98304.
#define AT_KV0  32768
#define AT_SMEM (98304 + 512)
#define NKV     (N_ / 64)

__global__ void __launch_bounds__(256, 1) flash_attn_mma(const int* __restrict__ kpm)
{
    const int tid = threadIdx.x, lane = tid & 31, w = tid >> 5;
    const int b = blockIdx.z, h = blockIdx.y;
    const int q0 = blockIdx.x << 7;
    const uint32_t sb = smem_u32(dyn_sm);
    const size_t hoff = ((size_t)b * H_ + h) * N_ * D_;
    float* mbuf = (float*)(dyn_sm + 98304);

    // stage Q hi/lo [128][64] (plain loads; once per block)
    {
        const __nv_bfloat16* qsrc[2] = {g_qh + hoff + (size_t)q0 * D_,
                                        g_ql + hoff + (size_t)q0 * D_};
#pragma unroll
        for (int i = 0; i < 8; i++) {
            const int gid = tid + i * 256;
            const int op = gid >> 10, g = gid & 1023;
            const int row = g >> 3, dg = g & 7;
            uint4 v = *(const uint4*)(qsrc[op] + row * 64 + dg * 8);
            *(uint4*)(dyn_sm + op * 16384 + swz(row * 128 + dg * 16)) = v;
        }
    }

    // K/V cp.async per-thread src/dst precompute
    const __nv_bfloat16* ksrc[4] = {g_kh + hoff, g_kl + hoff, g_vh + hoff, g_vl + hoff};
    const __nv_bfloat16* kgsrc[8];
    uint32_t ksdst[8];
#pragma unroll
    for (int i = 0; i < 8; i++) {
        const int gid = tid + i * 256;
        const int op = gid >> 9, g = gid & 511;
        const int row = g >> 3, dg = g & 7;
        kgsrc[i] = ksrc[op] + (size_t)row * D_ + dg * 8;
        ksdst[i] = AT_KV0 + op * 8192 + swz(row * 128 + dg * 16);
    }
    auto issue_kv = [&](int it) {
        const uint32_t stoff = (it & 1) * 32768;
#pragma unroll
        for (int i = 0; i < 8; i++)
            cp16(sb + stoff + ksdst[i], kgsrc[i] + it * 64 * D_);
        if (tid < 64)
            mbuf[(it & 1) * 64 + tid] =
                (kpm[b * N_ + it * 64 + tid] == 0) ? -1e9f : 0.0f;
    };

    issue_kv(0); CP_COMMIT();
    __syncthreads();

    // preload Q fragments (k = d, 4 k16 steps)
    uint32_t qfh[4][4], qfl[4][4];
    {
        const int rowQ = w * 16 + (lane & 15);
        const uint32_t base = rowQ * 128 + (lane >> 4) * 16;
#pragma unroll
        for (int ks = 0; ks < 4; ks++) {
            ldsm4(qfh[ks], sb + swz(base + ks * 32));
            ldsm4(qfl[ks], sb + 16384 + swz(base + ks * 32));
        }
    }

    float o[8][4];
#pragma unroll
    for (int j = 0; j < 8; j++)
#pragma unroll
        for (int q = 0; q < 4; q++) o[j][q] = 0.0f;
    float m0 = -INFINITY, m1 = -INFINITY, l0 = 0.0f, l1 = 0.0f;

    for (int it = 0; it < NKV; it++) {
        CP_WAIT(0);
        __syncthreads();
        if (it + 1 < NKV) issue_kv(it + 1);
        CP_COMMIT();

        const uint32_t kvb = sb + AT_KV0 + (it & 1) * 32768;
        const float* mb = mbuf + (it & 1) * 64;

        // ---- S = Q K^T (3-pass hi/lo) ----
        float s[8][4];
#pragma unroll
        for (int j = 0; j < 8; j++)
#pragma unroll
            for (int q = 0; q < 4; q++) s[j][q] = 0.0f;

#pragma unroll
        for (int ks = 0; ks < 4; ks++) {
#pragma unroll
            for (int np = 0; np < 4; np++) {
                const int nB = np * 16 + (lane & 7) + ((lane >> 4) << 3);
                const uint32_t ob = nB * 128 + ((lane >> 3) & 1) * 16 + ks * 32;
                uint32_t kb_h[4], kb_l[4];
                ldsm4(kb_h, kvb + swz(ob));
                ldsm4(kb_l, kvb + 8192 + swz(ob));
                mma16816(s[2 * np],     qfh[ks], kb_h[0], kb_h[1]);
                mma16816(s[2 * np + 1], qfh[ks], kb_h[2], kb_h[3]);
                mma16816(s[2 * np],     qfh[ks], kb_l[0], kb_l[1]);
                mma16816(s[2 * np + 1], qfh[ks], kb_l[2], kb_l[3]);
                mma16816(s[2 * np],     qfl[ks], kb_h[0], kb_h[1]);
                mma16816(s[2 * np + 1], qfl[ks], kb_h[2], kb_h[3]);
            }
        }

        // ---- scale + mask + online softmax ----
        const float scale = 0.125f;
        float mx0 = -INFINITY, mx1 = -INFINITY;
#pragma unroll
        for (int j = 0; j < 8; j++) {
            const int col = j * 8 + ((lane & 3) << 1);
            const float mb0 = mb[col], mb1 = mb[col + 1];
            s[j][0] = fmaf(s[j][0], scale, mb0);
            s[j][1] = fmaf(s[j][1], scale, mb1);
            s[j][2] = fmaf(s[j][2], scale, mb0);
            s[j][3] = fmaf(s[j][3], scale, mb1);
            mx0 = fmaxf(mx0, fmaxf(s[j][0], s[j][1]));
            mx1 = fmaxf(mx1, fmaxf(s[j][2], s[j][3]));
        }
        mx0 = fmaxf(mx0, __shfl_xor_sync(0xffffffffu, mx0, 1));
        mx0 = fmaxf(mx0, __shfl_xor_sync(0xffffffffu, mx0, 2));
        mx1 = fmaxf(mx1, __shfl_xor_sync(0xffffffffu, mx1, 1));
        mx1 = fmaxf(mx1, __shfl_xor_sync(0xffffffffu, mx1, 2));
        const float mn0 = fmaxf(m0, mx0), mn1 = fmaxf(m1, mx1);
        const float a0 = __expf(m0 - mn0), a1 = __expf(m1 - mn1);
        m0 = mn0; m1 = mn1;
        float s0 = 0.0f, s1 = 0.0f;
#pragma unroll
        for (int j = 0; j < 8; j++) {
            s[j][0] = __expf(s[j][0] - mn0);
            s[j][1] = __expf(s[j][1] - mn0);
            s[j][2] = __expf(s[j][2] - mn1);
            s[j][3] = __expf(s[j][3] - mn1);
            s0 += s[j][0] + s[j][1];
            s1 += s[j][2] + s[j][3];
        }
        s0 += __shfl_xor_sync(0xffffffffu, s0, 1);
        s0 += __shfl_xor_sync(0xffffffffu, s0, 2);
        s1 += __shfl_xor_sync(0xffffffffu, s1, 1);
        s1 += __shfl_xor_sync(0xffffffffu, s1, 2);
        l0 = l0 * a0 + s0;
        l1 = l1 * a1 + s1;
#pragma unroll
        for (int j = 0; j < 8; j++) {
            o[j][0] *= a0; o[j][1] *= a0;
            o[j][2] *= a1; o[j][3] *= a1;
        }

        // ---- pack P fragments (hi/lo) ----
        uint32_t ph[4][4], pl[4][4];
#pragma unroll
        for (int kt = 0; kt < 4; kt++) {
            const int t0 = 2 * kt, t1 = 2 * kt + 1;
            splitpack(s[t0][0], s[t0][1], ph[kt][0], pl[kt][0]);
            splitpack(s[t0][2], s[t0][3], ph[kt][1], pl[kt][1]);
            splitpack(s[t1][0], s[t1][1], ph[kt][2], pl[kt][2]);
            splitpack(s[t1][2], s[t1][3], ph[kt][3], pl[kt][3]);
        }

        // ---- O += P @ V (3-pass hi/lo), V via ldmatrix.trans ----
#pragma unroll
        for (int kt = 0; kt < 4; kt++) {
#pragma unroll
            for (int dp = 0; dp < 4; dp++) {
                const int kvr = kt * 16 + (lane & 15);
                const uint32_t ob = kvr * 128 + (dp * 2 + (lane >> 4)) * 16;
                uint32_t v_h[4], v_l[4];
                ldsm4t(v_h, kvb + 16384 + swz(ob));
                ldsm4t(v_l, kvb + 24576 + swz(ob));
                mma16816(o[2 * dp],     ph[kt], v_h[0], v_h[1]);
                mma16816(o[2 * dp + 1], ph[kt], v_h[2], v_h[3]);
                mma16816(o[2 * dp],     ph[kt], v_l[0], v_l[1]);
                mma16816(o[2 * dp + 1], ph[kt], v_l[2], v_l[3]);
                mma16816(o[2 * dp],     pl[kt], v_h[0], v_h[1]);
                mma16816(o[2 * dp + 1], pl[kt], v_h[2], v_h[3]);
            }
        }
    }

    // ---- normalize + hi/lo split -> g_aoh/g_aol [b][n][h*64+d] ----
    const float li0 = 1.0f / l0, li1 = 1.0f / l1;
    const int n0 = q0 + w * 16 + (lane >> 2);
    const size_t ro0 = (size_t)(b * N_ + n0) * C_ + h * D_;
    const size_t ro1 = ro0 + (size_t)8 * C_;
#pragma unroll
    for (int j = 0; j < 8; j++) {
        const int col = j * 8 + ((lane & 3) << 1);
        uint32_t Hw, Lw;
        splitpack(o[j][0] * li0, o[j][1] * li0, Hw, Lw);
        *(uint32_t*)(g_aoh + ro0 + col) = Hw;
        *(uint32_t*)(g_aol + ro0 + col) = Lw;
        splitpack(o[j][2] * li1, o[j][3] * li1, Hw, Lw);
        *(uint32_t*)(g_aoh + ro1 + col) = Hw;
        *(uint32_t*)(g_aol + ro1 + col) = Lw;
    }
}

// ---------------------------------------------------------------------------
extern "C" void kernel_launch(void* const* d_in, const int* in_sizes, int n_in,
                              void* d_out, int out_size)
{
    const float* x      = (const float*)d_in[0];
    const float* w_qkv  = (const float*)d_in[1];
    const float* w_proj = (const float*)d_in[2];
    const float* b_proj = (const float*)d_in[3];
    const int*   kpm    = (const int*)d_in[4];
    float* out = (float*)d_out;

    float* qkv;
    __nv_bfloat16 *xh, *xl, *wqh, *wql, *wph, *wpl, *aoh, *aol;
    cudaGetSymbolAddress((void**)&qkv, g_qkv);
    cudaGetSymbolAddress((void**)&xh,  g_xh);
    cudaGetSymbolAddress((void**)&xl,  g_xl);
    cudaGetSymbolAddress((void**)&wqh, g_wqh);
    cudaGetSymbolAddress((void**)&wql, g_wql);
    cudaGetSymbolAddress((void**)&wph, g_wph);
    cudaGetSymbolAddress((void**)&wpl, g_wpl);
    cudaGetSymbolAddress((void**)&aoh, g_aoh);
    cudaGetSymbolAddress((void**)&aol, g_aol);

    // 0) split fp32 -> bf16 hi/lo
    cvt_hilo<<<(M_ * C_ / 4 + 255) / 256, 256>>>(
        (const float4*)x, (uint2*)xh, (uint2*)xl, M_ * C_ / 4);
    cvt_hilo<<<(QKVN * C_ / 4 + 255) / 256, 256>>>(
        (const float4*)w_qkv, (uint2*)wqh, (uint2*)wql, QKVN * C_ / 4);
    cvt_hilo<<<(C_ * C_ / 4 + 255) / 256, 256>>>(
        (const float4*)w_proj, (uint2*)wph, (uint2*)wpl, C_ * C_ / 4);

    // 1) qkv = x @ w_qkv^T (mma.sync bf16 3-pass, cp.async pipeline)
    cudaFuncSetAttribute(gemm_mma, cudaFuncAttributeMaxDynamicSharedMemorySize, G_SMEM);
    gemm_mma<<<dim3(QKVN / 128, M_ / 128), 256, G_SMEM>>>(
        xh, xl, wqh, wql, nullptr, qkv, QKVN);

    // 2) RoPE + split -> per-head hi/lo bf16
    rope_split<<<M_, 512>>>();

    // 3) flash attention (mma.sync, cp.async double buffer)
    cudaFuncSetAttribute(flash_attn_mma, cudaFuncAttributeMaxDynamicSharedMemorySize,
                         AT_SMEM);
    flash_attn_mma<<<dim3(N_ / 128, H_, B_), 256, AT_SMEM>>>(kpm);

    // 4) out = ao @ w_proj^T + b_proj
    gemm_mma<<<dim3(C_ / 128, M_ / 128), 256, G_SMEM>>>(
        aoh, aol, wph, wpl, b_proj, out, C_);
}

// round 9
// speedup vs baseline: 3.1000x; 1.0089x over previous
#include <cuda_runtime.h>
#include <cuda_bf16.h>
#include <math.h>
#include <stdint.h>

#define B_   2
#define N_   2048
#define C_   1024
#define H_   16
#define D_   64
#define M_   (B_ * N_)      // 4096
#define QKVN 3072

// ---------------- mma.sync / ldmatrix helpers (portable PTX) ----------------
__device__ __forceinline__ uint32_t smem_u32(const void* p) {
    uint32_t a;
    asm("{ .reg .u64 t; cvta.to.shared.u64 t, %1; cvt.u32.u64 %0, t; }"
        : "=r"(a) : "l"(p));
    return a;
}
__device__ __forceinline__ uint32_t swz(uint32_t off) {  // SW128: bits[6:4] ^= bits[9:7]
    return off ^ ((off >> 3) & 0x70);
}
__device__ __forceinline__ void ldsm4(uint32_t* r, uint32_t addr) {
    asm volatile("ldmatrix.sync.aligned.m8n8.x4.shared.b16 {%0,%1,%2,%3}, [%4];"
                 : "=r"(r[0]), "=r"(r[1]), "=r"(r[2]), "=r"(r[3]) : "r"(addr));
}
__device__ __forceinline__ void ldsm4t(uint32_t* r, uint32_t addr) {
    asm volatile("ldmatrix.sync.aligned.m8n8.x4.trans.shared.b16 {%0,%1,%2,%3}, [%4];"
                 : "=r"(r[0]), "=r"(r[1]), "=r"(r[2]), "=r"(r[3]) : "r"(addr));
}
__device__ __forceinline__ void mma16816(float* d, const uint32_t* a,
                                         uint32_t b0, uint32_t b1) {
    asm volatile(
        "mma.sync.aligned.m16n8k16.row.col.f32.bf16.bf16.f32 "
        "{%0,%1,%2,%3}, {%4,%5,%6,%7}, {%8,%9}, {%0,%1,%2,%3};"
        : "+f"(d[0]), "+f"(d[1]), "+f"(d[2]), "+f"(d[3])
        : "r"(a[0]), "r"(a[1]), "r"(a[2]), "r"(a[3]), "r"(b0), "r"(b1));
}
__device__ __forceinline__ void cp16(uint32_t sdst, const void* gsrc) {
    asm volatile("cp.async.cg.shared.global [%0], [%1], 16;"
                 :: "r"(sdst), "l"(gsrc) : "memory");
}
#define CP_COMMIT() asm volatile("cp.async.commit_group;" ::: "memory")
#define CP_WAIT(n)  asm volatile("cp.async.wait_group %0;" :: "n"(n) : "memory")

// split two floats into packed (hi, lo) bf16x2 words
__device__ __forceinline__ void splitpack(float x, float y, uint32_t& Hw, uint32_t& Lw) {
    __nv_bfloat16 hx = __float2bfloat16(x), hy = __float2bfloat16(y);
    __nv_bfloat16 lx = __float2bfloat16(x - __bfloat162float(hx));
    __nv_bfloat16 ly = __float2bfloat16(y - __bfloat162float(hy));
    Hw = (uint32_t)__bfloat16_as_ushort(hx) | ((uint32_t)__bfloat16_as_ushort(hy) << 16);
    Lw = (uint32_t)__bfloat16_as_ushort(lx) | ((uint32_t)__bfloat16_as_ushort(ly) << 16);
}

// ---------------- scratch ----------------------------------------------------
__device__ float g_qkv[(size_t)M_ * QKVN];                  // 48 MB
__device__ __nv_bfloat16 g_xh[(size_t)M_ * C_];
__device__ __nv_bfloat16 g_xl[(size_t)M_ * C_];
__device__ __nv_bfloat16 g_wqh[(size_t)QKVN * C_];
__device__ __nv_bfloat16 g_wql[(size_t)QKVN * C_];
__device__ __nv_bfloat16 g_wph[(size_t)C_ * C_];
__device__ __nv_bfloat16 g_wpl[(size_t)C_ * C_];
__device__ __nv_bfloat16 g_qh[(size_t)B_ * H_ * N_ * D_];
__device__ __nv_bfloat16 g_ql[(size_t)B_ * H_ * N_ * D_];
__device__ __nv_bfloat16 g_kh[(size_t)B_ * H_ * N_ * D_];
__device__ __nv_bfloat16 g_kl[(size_t)B_ * H_ * N_ * D_];
__device__ __nv_bfloat16 g_vh[(size_t)B_ * H_ * N_ * D_];
__device__ __nv_bfloat16 g_vl[(size_t)B_ * H_ * N_ * D_];
__device__ __nv_bfloat16 g_aoh[(size_t)M_ * C_];
__device__ __nv_bfloat16 g_aol[(size_t)M_ * C_];

extern __shared__ __align__(1024) char dyn_sm[];

// ---------------- fp32 -> (hi, lo) bf16 split --------------------------------
__global__ void __launch_bounds__(256) cvt_hilo(
    const float4* __restrict__ src, uint2* __restrict__ hi,
    uint2* __restrict__ lo, int n4)
{
    int i = blockIdx.x * 256 + threadIdx.x;
    if (i >= n4) return;
    float4 v = src[i];
    uint2 Hv, Lv;
    splitpack(v.x, v.y, Hv.x, Lv.x);
    splitpack(v.z, v.w, Hv.y, Lv.y);
    hi[i] = Hv;
    lo[i] = Lv;
}

// ---------------- GEMM: C = A @ B^T (+bias), bf16 hi/lo 3-pass mma ----------
// cp.async 4-stage pipeline. Block tile 128x128, kc=32, stage=32KB (4 ops).
// Inner loop pass-major: hh over 16 indep accs, then hl, then lh.
#define G_STAGE 32768
#define G_SMEM  (4 * G_STAGE)          // 131072

__global__ void __launch_bounds__(256, 1) gemm_mma(
    const __nv_bfloat16* __restrict__ Ah, const __nv_bfloat16* __restrict__ Al,
    const __nv_bfloat16* __restrict__ Bh, const __nv_bfloat16* __restrict__ Bl,
    const float* __restrict__ bias, float* __restrict__ C, int Nn)
{
    const int tid = threadIdx.x, lane = tid & 31, w = tid >> 5;
    const int wm = w >> 1, wn = w & 1;
    const int bm = blockIdx.y << 7, bn = blockIdx.x << 7;
    const uint32_t sb = smem_u32(dyn_sm);

    float acc[2][8][4];
#pragma unroll
    for (int mt = 0; mt < 2; mt++)
#pragma unroll
        for (int j = 0; j < 8; j++)
#pragma unroll
            for (int q = 0; q < 4; q++) acc[mt][j][q] = 0.0f;

    uint32_t offA[2], offB[4];
#pragma unroll
    for (int mt = 0; mt < 2; mt++) {
        const int rowA = wm * 32 + mt * 16 + (lane & 15);
        offA[mt] = rowA * 64 + (lane >> 4) * 16;
    }
#pragma unroll
    for (int np = 0; np < 4; np++) {
        const int nB = wn * 64 + np * 16 + (lane & 7) + ((lane >> 4) << 3);
        offB[np] = nB * 64 + ((lane >> 3) & 1) * 16;
    }

    const __nv_bfloat16* srcs[4] = {Ah, Al, Bh, Bl};
    const __nv_bfloat16* gsrc[8];
    uint32_t sdst[8];
#pragma unroll
    for (int i = 0; i < 8; i++) {
        const int gid = tid + i * 256;
        const int op = gid >> 9, g = gid & 511;
        const int row = g >> 2, kg = g & 3;
        const int rb = (op < 2) ? bm : bn;
        gsrc[i] = srcs[op] + (size_t)(rb + row) * C_ + kg * 8;
        sdst[i] = op * 8192 + swz(row * 64 + kg * 16);
    }

    auto issue = [&](int c) {
        const uint32_t stb = sb + (c & 3) * G_STAGE;
#pragma unroll
        for (int i = 0; i < 8; i++)
            cp16(stb + sdst[i], gsrc[i] + c * 32);
    };

    issue(0); CP_COMMIT();
    issue(1); CP_COMMIT();
    issue(2); CP_COMMIT();

    for (int c = 0; c < 32; c++) {
        CP_WAIT(2);
        __syncthreads();
        if (c + 3 < 32) issue(c + 3);
        CP_COMMIT();

        const uint32_t stb = sb + (c & 3) * G_STAGE;
#pragma unroll
        for (int ks = 0; ks < 2; ks++) {
            uint32_t a_h[2][4], a_l[2][4];
#pragma unroll
            for (int mt = 0; mt < 2; mt++) {
                ldsm4(a_h[mt], stb + swz(offA[mt] + ks * 32));
                ldsm4(a_l[mt], stb + 8192 + swz(offA[mt] + ks * 32));
            }
            uint32_t b_h[4][4], b_l[4][4];
#pragma unroll
            for (int np = 0; np < 4; np++) {
                ldsm4(b_h[np], stb + 16384 + swz(offB[np] + ks * 32));
                ldsm4(b_l[np], stb + 24576 + swz(offB[np] + ks * 32));
            }
            // pass 1: hi * hi (16 independent accumulators)
#pragma unroll
            for (int np = 0; np < 4; np++)
#pragma unroll
                for (int mt = 0; mt < 2; mt++) {
                    mma16816(acc[mt][2 * np],     a_h[mt], b_h[np][0], b_h[np][1]);
                    mma16816(acc[mt][2 * np + 1], a_h[mt], b_h[np][2], b_h[np][3]);
                }
            // pass 2: hi * lo
#pragma unroll
            for (int np = 0; np < 4; np++)
#pragma unroll
                for (int mt = 0; mt < 2; mt++) {
                    mma16816(acc[mt][2 * np],     a_h[mt], b_l[np][0], b_l[np][1]);
                    mma16816(acc[mt][2 * np + 1], a_h[mt], b_l[np][2], b_l[np][3]);
                }
            // pass 3: lo * hi
#pragma unroll
            for (int np = 0; np < 4; np++)
#pragma unroll
                for (int mt = 0; mt < 2; mt++) {
                    mma16816(acc[mt][2 * np],     a_l[mt], b_h[np][0], b_h[np][1]);
                    mma16816(acc[mt][2 * np + 1], a_l[mt], b_h[np][2], b_h[np][3]);
                }
        }
    }

#pragma unroll
    for (int mt = 0; mt < 2; mt++)
#pragma unroll
        for (int j = 0; j < 8; j++) {
            const int row = bm + wm * 32 + mt * 16 + (lane >> 2);
            const int col = bn + wn * 64 + j * 8 + ((lane & 3) << 1);
            const float b0 = bias ? bias[col] : 0.0f;
            const float b1 = bias ? bias[col + 1] : 0.0f;
            float2 v0 = make_float2(acc[mt][j][0] + b0, acc[mt][j][1] + b1);
            float2 v1 = make_float2(acc[mt][j][2] + b0, acc[mt][j][3] + b1);
            *(float2*)(C + (size_t)row * Nn + col) = v0;
            *(float2*)(C + (size_t)(row + 8) * Nn + col) = v1;
        }
}

// ---------------- RoPE + split -> q/k/v hi/lo bf16 [b][h][n][d] -------------
__global__ void __launch_bounds__(512) rope_split()
{
    const int m = blockIdx.x;
    const int b = m >> 11, n = m & (N_ - 1);
    const int h = threadIdx.x >> 5;
    const int i = threadIdx.x & 31;

    const float* row = g_qkv + (size_t)m * QKVN;
    const int c = h * D_;
    float q0 = row[c + i],            q1 = row[c + i + 32];
    float k0 = row[C_ + c + i],       k1 = row[C_ + c + i + 32];
    float v0 = row[2 * C_ + c + i],   v1 = row[2 * C_ + c + i + 32];

    float inv = exp2f(-11.0f * (float)i * (1.0f / 32.0f));  // 2048^(-i/32)
    float th = (float)n * inv;
    float cs = cosf(th), sn = sinf(th);

    float qa = q0 * cs - q1 * sn, qb = q1 * cs + q0 * sn;
    float ka = k0 * cs - k1 * sn, kb = k1 * cs + k0 * sn;

    size_t base = (((size_t)b * H_ + h) * N_ + n) * D_;
    const float vals[6] = {qa, qb, ka, kb, v0, v1};
    __nv_bfloat16* Hp[6] = {g_qh + base + i, g_qh + base + i + 32,
                            g_kh + base + i, g_kh + base + i + 32,
                            g_vh + base + i, g_vh + base + i + 32};
    __nv_bfloat16* Lp[6] = {g_ql + base + i, g_ql + base + i + 32,
                            g_kl + base + i, g_kl + base + i + 32,
                            g_vl + base + i, g_vl + base + i + 32};
#pragma unroll
    for (int t = 0; t < 6; t++) {
        __nv_bfloat16 hv = __float2bfloat16(vals[t]);
        *Hp[t] = hv;
        *Lp[t] = __float2bfloat16(vals[t] - __bfloat162float(hv));
    }
}

// ---------------- flash attention with mma.sync, BQ=128 BKV=64 --------------
// cp.async double-buffered K/V stages; pass-major MMA ordering.
#define AT_KV0  32768
#define AT_SMEM (98304 + 512)
#define NKV     (N_ / 64)

__global__ void __launch_bounds__(256, 1) flash_attn_mma(const int* __restrict__ kpm)
{
    const int tid = threadIdx.x, lane = tid & 31, w = tid >> 5;
    const int b = blockIdx.z, h = blockIdx.y;
    const int q0 = blockIdx.x << 7;
    const uint32_t sb = smem_u32(dyn_sm);
    const size_t hoff = ((size_t)b * H_ + h) * N_ * D_;
    float* mbuf = (float*)(dyn_sm + 98304);

    // stage Q hi/lo [128][64]
    {
        const __nv_bfloat16* qsrc[2] = {g_qh + hoff + (size_t)q0 * D_,
                                        g_ql + hoff + (size_t)q0 * D_};
#pragma unroll
        for (int i = 0; i < 8; i++) {
            const int gid = tid + i * 256;
            const int op = gid >> 10, g = gid & 1023;
            const int row = g >> 3, dg = g & 7;
            uint4 v = *(const uint4*)(qsrc[op] + row * 64 + dg * 8);
            *(uint4*)(dyn_sm + op * 16384 + swz(row * 128 + dg * 16)) = v;
        }
    }

    const __nv_bfloat16* ksrc[4] = {g_kh + hoff, g_kl + hoff, g_vh + hoff, g_vl + hoff};
    const __nv_bfloat16* kgsrc[8];
    uint32_t ksdst[8];
#pragma unroll
    for (int i = 0; i < 8; i++) {
        const int gid = tid + i * 256;
        const int op = gid >> 9, g = gid & 511;
        const int row = g >> 3, dg = g & 7;
        kgsrc[i] = ksrc[op] + (size_t)row * D_ + dg * 8;
        ksdst[i] = AT_KV0 + op * 8192 + swz(row * 128 + dg * 16);
    }
    auto issue_kv = [&](int it) {
        const uint32_t stoff = (it & 1) * 32768;
#pragma unroll
        for (int i = 0; i < 8; i++)
            cp16(sb + stoff + ksdst[i], kgsrc[i] + it * 64 * D_);
        if (tid < 64)
            mbuf[(it & 1) * 64 + tid] =
                (kpm[b * N_ + it * 64 + tid] == 0) ? -1e9f : 0.0f;
    };

    issue_kv(0); CP_COMMIT();
    __syncthreads();

    // preload Q fragments
    uint32_t qfh[4][4], qfl[4][4];
    {
        const int rowQ = w * 16 + (lane & 15);
        const uint32_t base = rowQ * 128 + (lane >> 4) * 16;
#pragma unroll
        for (int ks = 0; ks < 4; ks++) {
            ldsm4(qfh[ks], sb + swz(base + ks * 32));
            ldsm4(qfl[ks], sb + 16384 + swz(base + ks * 32));
        }
    }

    float o[8][4];
#pragma unroll
    for (int j = 0; j < 8; j++)
#pragma unroll
        for (int q = 0; q < 4; q++) o[j][q] = 0.0f;
    float m0 = -INFINITY, m1 = -INFINITY, l0 = 0.0f, l1 = 0.0f;

    for (int it = 0; it < NKV; it++) {
        CP_WAIT(0);
        __syncthreads();
        if (it + 1 < NKV) issue_kv(it + 1);
        CP_COMMIT();

        const uint32_t kvb = sb + AT_KV0 + (it & 1) * 32768;
        const float* mb = mbuf + (it & 1) * 64;

        // ---- S = Q K^T (3-pass hi/lo), pass-major per ks ----
        float s[8][4];
#pragma unroll
        for (int j = 0; j < 8; j++)
#pragma unroll
            for (int q = 0; q < 4; q++) s[j][q] = 0.0f;

#pragma unroll
        for (int ks = 0; ks < 4; ks++) {
            uint32_t kb_h[4][4], kb_l[4][4];
#pragma unroll
            for (int np = 0; np < 4; np++) {
                const int nB = np * 16 + (lane & 7) + ((lane >> 4) << 3);
                const uint32_t ob = nB * 128 + ((lane >> 3) & 1) * 16 + ks * 32;
                ldsm4(kb_h[np], kvb + swz(ob));
                ldsm4(kb_l[np], kvb + 8192 + swz(ob));
            }
#pragma unroll
            for (int np = 0; np < 4; np++) {
                mma16816(s[2 * np],     qfh[ks], kb_h[np][0], kb_h[np][1]);
                mma16816(s[2 * np + 1], qfh[ks], kb_h[np][2], kb_h[np][3]);
            }
#pragma unroll
            for (int np = 0; np < 4; np++) {
                mma16816(s[2 * np],     qfh[ks], kb_l[np][0], kb_l[np][1]);
                mma16816(s[2 * np + 1], qfh[ks], kb_l[np][2], kb_l[np][3]);
            }
#pragma unroll
            for (int np = 0; np < 4; np++) {
                mma16816(s[2 * np],     qfl[ks], kb_h[np][0], kb_h[np][1]);
                mma16816(s[2 * np + 1], qfl[ks], kb_h[np][2], kb_h[np][3]);
            }
        }

        // ---- scale + mask + online softmax ----
        const float scale = 0.125f;
        float mx0 = -INFINITY, mx1 = -INFINITY;
#pragma unroll
        for (int j = 0; j < 8; j++) {
            const int col = j * 8 + ((lane & 3) << 1);
            const float mb0 = mb[col], mb1 = mb[col + 1];
            s[j][0] = fmaf(s[j][0], scale, mb0);
            s[j][1] = fmaf(s[j][1], scale, mb1);
            s[j][2] = fmaf(s[j][2], scale, mb0);
            s[j][3] = fmaf(s[j][3], scale, mb1);
            mx0 = fmaxf(mx0, fmaxf(s[j][0], s[j][1]));
            mx1 = fmaxf(mx1, fmaxf(s[j][2], s[j][3]));
        }
        mx0 = fmaxf(mx0, __shfl_xor_sync(0xffffffffu, mx0, 1));
        mx0 = fmaxf(mx0, __shfl_xor_sync(0xffffffffu, mx0, 2));
        mx1 = fmaxf(mx1, __shfl_xor_sync(0xffffffffu, mx1, 1));
        mx1 = fmaxf(mx1, __shfl_xor_sync(0xffffffffu, mx1, 2));
        const float mn0 = fmaxf(m0, mx0), mn1 = fmaxf(m1, mx1);
        const float a0 = __expf(m0 - mn0), a1 = __expf(m1 - mn1);
        m0 = mn0; m1 = mn1;
        float s0 = 0.0f, s1 = 0.0f;
#pragma unroll
        for (int j = 0; j < 8; j++) {
            s[j][0] = __expf(s[j][0] - mn0);
            s[j][1] = __expf(s[j][1] - mn0);
            s[j][2] = __expf(s[j][2] - mn1);
            s[j][3] = __expf(s[j][3] - mn1);
            s0 += s[j][0] + s[j][1];
            s1 += s[j][2] + s[j][3];
        }
        s0 += __shfl_xor_sync(0xffffffffu, s0, 1);
        s0 += __shfl_xor_sync(0xffffffffu, s0, 2);
        s1 += __shfl_xor_sync(0xffffffffu, s1, 1);
        s1 += __shfl_xor_sync(0xffffffffu, s1, 2);
        l0 = l0 * a0 + s0;
        l1 = l1 * a1 + s1;
#pragma unroll
        for (int j = 0; j < 8; j++) {
            o[j][0] *= a0; o[j][1] *= a0;
            o[j][2] *= a1; o[j][3] *= a1;
        }

        // ---- pack P fragments (hi/lo) ----
        uint32_t ph[4][4], pl[4][4];
#pragma unroll
        for (int kt = 0; kt < 4; kt++) {
            const int t0 = 2 * kt, t1 = 2 * kt + 1;
            splitpack(s[t0][0], s[t0][1], ph[kt][0], pl[kt][0]);
            splitpack(s[t0][2], s[t0][3], ph[kt][1], pl[kt][1]);
            splitpack(s[t1][0], s[t1][1], ph[kt][2], pl[kt][2]);
            splitpack(s[t1][2], s[t1][3], ph[kt][3], pl[kt][3]);
        }

        // ---- O += P @ V (3-pass hi/lo), pass-major per kt ----
#pragma unroll
        for (int kt = 0; kt < 4; kt++) {
            uint32_t v_h[4][4], v_l[4][4];
#pragma unroll
            for (int dp = 0; dp < 4; dp++) {
                const int kvr = kt * 16 + (lane & 15);
                const uint32_t ob = kvr * 128 + (dp * 2 + (lane >> 4)) * 16;
                ldsm4t(v_h[dp], kvb + 16384 + swz(ob));
                ldsm4t(v_l[dp], kvb + 24576 + swz(ob));
            }
#pragma unroll
            for (int dp = 0; dp < 4; dp++) {
                mma16816(o[2 * dp],     ph[kt], v_h[dp][0], v_h[dp][1]);
                mma16816(o[2 * dp + 1], ph[kt], v_h[dp][2], v_h[dp][3]);
            }
#pragma unroll
            for (int dp = 0; dp < 4; dp++) {
                mma16816(o[2 * dp],     ph[kt], v_l[dp][0], v_l[dp][1]);
                mma16816(o[2 * dp + 1], ph[kt], v_l[dp][2], v_l[dp][3]);
            }
#pragma unroll
            for (int dp = 0; dp < 4; dp++) {
                mma16816(o[2 * dp],     pl[kt], v_h[dp][0], v_h[dp][1]);
                mma16816(o[2 * dp + 1], pl[kt], v_h[dp][2], v_h[dp][3]);
            }
        }
    }

    // ---- normalize + hi/lo split -> g_aoh/g_aol ----
    const float li0 = 1.0f / l0, li1 = 1.0f / l1;
    const int n0 = q0 + w * 16 + (lane >> 2);
    const size_t ro0 = (size_t)(b * N_ + n0) * C_ + h * D_;
    const size_t ro1 = ro0 + (size_t)8 * C_;
#pragma unroll
    for (int j = 0; j < 8; j++) {
        const int col = j * 8 + ((lane & 3) << 1);
        uint32_t Hw, Lw;
        splitpack(o[j][0] * li0, o[j][1] * li0, Hw, Lw);
        *(uint32_t*)(g_aoh + ro0 + col) = Hw;
        *(uint32_t*)(g_aol + ro0 + col) = Lw;
        splitpack(o[j][2] * li1, o[j][3] * li1, Hw, Lw);
        *(uint32_t*)(g_aoh + ro1 + col) = Hw;
        *(uint32_t*)(g_aol + ro1 + col) = Lw;
    }
}

// ---------------------------------------------------------------------------
extern "C" void kernel_launch(void* const* d_in, const int* in_sizes, int n_in,
                              void* d_out, int out_size)
{
    const float* x      = (const float*)d_in[0];
    const float* w_qkv  = (const float*)d_in[1];
    const float* w_proj = (const float*)d_in[2];
    const float* b_proj = (const float*)d_in[3];
    const int*   kpm    = (const int*)d_in[4];
    float* out = (float*)d_out;

    float* qkv;
    __nv_bfloat16 *xh, *xl, *wqh, *wql, *wph, *wpl, *aoh, *aol;
    cudaGetSymbolAddress((void**)&qkv, g_qkv);
    cudaGetSymbolAddress((void**)&xh,  g_xh);
    cudaGetSymbolAddress((void**)&xl,  g_xl);
    cudaGetSymbolAddress((void**)&wqh, g_wqh);
    cudaGetSymbolAddress((void**)&wql, g_wql);
    cudaGetSymbolAddress((void**)&wph, g_wph);
    cudaGetSymbolAddress((void**)&wpl, g_wpl);
    cudaGetSymbolAddress((void**)&aoh, g_aoh);
    cudaGetSymbolAddress((void**)&aol, g_aol);

    // 0) split fp32 -> bf16 hi/lo
    cvt_hilo<<<(M_ * C_ / 4 + 255) / 256, 256>>>(
        (const float4*)x, (uint2*)xh, (uint2*)xl, M_ * C_ / 4);
    cvt_hilo<<<(QKVN * C_ / 4 + 255) / 256, 256>>>(
        (const float4*)w_qkv, (uint2*)wqh, (uint2*)wql, QKVN * C_ / 4);
    cvt_hilo<<<(C_ * C_ / 4 + 255) / 256, 256>>>(
        (const float4*)w_proj, (uint2*)wph, (uint2*)wpl, C_ * C_ / 4);

    // 1) qkv = x @ w_qkv^T
    cudaFuncSetAttribute(gemm_mma, cudaFuncAttributeMaxDynamicSharedMemorySize, G_SMEM);
    gemm_mma<<<dim3(QKVN / 128, M_ / 128), 256, G_SMEM>>>(
        xh, xl, wqh, wql, nullptr, qkv, QKVN);

    // 2) RoPE + split
    rope_split<<<M_, 512>>>();

    // 3) flash attention
    cudaFuncSetAttribute(flash_attn_mma, cudaFuncAttributeMaxDynamicSharedMemorySize,
                         AT_SMEM);
    flash_attn_mma<<<dim3(N_ / 128, H_, B_), 256, AT_SMEM>>>(kpm);

    // 4) out = ao @ w_proj^T + b_proj
    gemm_mma<<<dim3(C_ / 128, M_ / 128), 256, G_SMEM>>>(
        aoh, aol, wph, wpl, b_proj, out, C_);
}